// round 3
// baseline (speedup 1.0000x reference)
#include <cuda_runtime.h>
#include <cstdint>
#include <cstddef>

#define BATCH 2
#define WTOT  2048
#define CDIM  1024
#define HEADS 16
#define HD    64

// Scratch (no allocation allowed): proj output (B,W,2C) = 32MB, nudged (B,W,C) = 16MB
__device__ float g_all[(size_t)BATCH * WTOT * 2 * CDIM];
__device__ float g_nudged[(size_t)BATCH * WTOT * CDIM];

// ----------------------------------------------------------------------------
// C[M,N] = A[M,K] @ B[N,K]^T  (all row-major; M,N multiples of 128, K of 16)
// 128x128 tile, 16 k-step, 256 threads, 8x8 register microtile.
// ----------------------------------------------------------------------------
__global__ __launch_bounds__(256, 2) void sgemm_abt(const float* __restrict__ A,
                                                    const float* __restrict__ B,
                                                    float* __restrict__ C,
                                                    int M, int N, int K)
{
    __shared__ float As[16][132];
    __shared__ float Bs[16][132];

    const int t  = threadIdx.x;
    const int tx = t & 15;
    const int ty = t >> 4;
    const int m0 = blockIdx.y * 128;
    const int n0 = blockIdx.x * 128;

    float acc[8][8];
#pragma unroll
    for (int i = 0; i < 8; i++)
#pragma unroll
        for (int j = 0; j < 8; j++) acc[i][j] = 0.f;

    for (int k0 = 0; k0 < K; k0 += 16) {
        // Load 128x16 tiles of A and B, transposed into [k][row] layout.
#pragma unroll
        for (int i = 0; i < 2; i++) {
            int idx = i * 256 + t;          // 512 float4 per tile
            int row = idx >> 2;             // 4 float4 per row of 16 k
            int kq  = (idx & 3) << 2;
            float4 a4 = *(const float4*)(A + (size_t)(m0 + row) * K + k0 + kq);
            As[kq + 0][row] = a4.x;
            As[kq + 1][row] = a4.y;
            As[kq + 2][row] = a4.z;
            As[kq + 3][row] = a4.w;
            float4 b4 = *(const float4*)(B + (size_t)(n0 + row) * K + k0 + kq);
            Bs[kq + 0][row] = b4.x;
            Bs[kq + 1][row] = b4.y;
            Bs[kq + 2][row] = b4.z;
            Bs[kq + 3][row] = b4.w;
        }
        __syncthreads();

#pragma unroll
        for (int k = 0; k < 16; k++) {
            float a[8], b[8];
            *(float4*)(a)     = *(const float4*)&As[k][ty * 8];
            *(float4*)(a + 4) = *(const float4*)&As[k][ty * 8 + 4];
            *(float4*)(b)     = *(const float4*)&Bs[k][tx * 8];
            *(float4*)(b + 4) = *(const float4*)&Bs[k][tx * 8 + 4];
#pragma unroll
            for (int i = 0; i < 8; i++)
#pragma unroll
                for (int j = 0; j < 8; j++)
                    acc[i][j] += a[i] * b[j];
        }
        __syncthreads();
    }

#pragma unroll
    for (int i = 0; i < 8; i++) {
        float* cp = C + (size_t)(m0 + ty * 8 + i) * N + n0 + tx * 8;
        *(float4*)cp       = make_float4(acc[i][0], acc[i][1], acc[i][2], acc[i][3]);
        *(float4*)(cp + 4) = make_float4(acc[i][4], acc[i][5], acc[i][6], acc[i][7]);
    }
}

// ----------------------------------------------------------------------------
// Fused causal "attention" (no softmax; masked entries are ZERO):
//   per (b,h):  S = (Q @ Q^T) / 8, S[q][s]=0 for s>q;  nudged = S @ V
// Q/V rows live inside g_all:   Q(b,h,w,:) = all[b][w][h*64 : h*64+64]
//                               V(b,h,w,:) = all[b][w][1024 + h*64 : ...]
// One CTA = one (b,h, 128-row q-tile). Scores never leave SMEM.
// Output written directly in (b, w, c) layout for the final GEMM.
//
// SMEM: Qs [64][132]  (k-major Q tile, q=0..127)
//       Vs [64][68]   (s-major V tile)
//       U  [64*132]   union: Ks [k][68]  <->  St [s][132]
// ----------------------------------------------------------------------------
#define QS_STR 132
#define KS_STR 68
#define VS_STR 68
#define ST_STR 132
#define SM_QS_OFF 0
#define SM_VS_OFF (64 * 132)
#define SM_U_OFF  (64 * 132 + 64 * 68)
#define SM_FLOATS (64 * 132 + 64 * 68 + 64 * 132)

__global__ __launch_bounds__(256, 2) void attn_kernel(const float* __restrict__ all,
                                                      float* __restrict__ nudged)
{
    extern __shared__ float sm[];
    float* Qs = sm + SM_QS_OFF;
    float* Vs = sm + SM_VS_OFF;
    float* U  = sm + SM_U_OFF;

    const int t  = threadIdx.x;
    const int tx = t & 15;
    const int ty = t >> 4;
    const int q0 = blockIdx.x * 128;
    const int b  = blockIdx.y >> 4;
    const int h  = blockIdx.y & 15;

    const float* inp  = all + (size_t)b * WTOT * 2 * CDIM + h * HD; // +w*2048 per row
    const float* vinp = inp + CDIM;

    // Load Q tile (128 rows x 64 k) transposed into Qs[k][q]
#pragma unroll
    for (int i = 0; i < 8; i++) {
        int idx = i * 256 + t;              // 2048 float4
        int q   = idx >> 4;                 // 16 float4 per row
        int kq  = (idx & 15) << 2;
        float4 v = *(const float4*)(inp + (size_t)(q0 + q) * 2048 + kq);
        Qs[(kq + 0) * QS_STR + q] = v.x;
        Qs[(kq + 1) * QS_STR + q] = v.y;
        Qs[(kq + 2) * QS_STR + q] = v.z;
        Qs[(kq + 3) * QS_STR + q] = v.w;
    }

    const int rq = ty * 8;                  // this thread's 8 q-rows
    const int c4 = tx * 4;                  // this thread's 4 s-cols / n-cols
    float acc[8][4];
#pragma unroll
    for (int i = 0; i < 8; i++)
#pragma unroll
        for (int j = 0; j < 4; j++) acc[i][j] = 0.f;

    const int nS = (q0 >> 6) + 2;           // s-blocks of 64 up to the diagonal
    for (int sb = 0; sb < nS; sb++) {
        const int s0 = sb << 6;
        __syncthreads();                    // U(St) / Vs free to overwrite

        // Load K tile transposed -> U as Ks[k][s]; V tile straight -> Vs[s][n]
#pragma unroll
        for (int i = 0; i < 4; i++) {
            int idx = i * 256 + t;          // 1024 float4 per operand
            int r   = idx >> 4;
            int kq  = (idx & 15) << 2;
            float4 kv = *(const float4*)(inp + (size_t)(s0 + r) * 2048 + kq);
            U[(kq + 0) * KS_STR + r] = kv.x;
            U[(kq + 1) * KS_STR + r] = kv.y;
            U[(kq + 2) * KS_STR + r] = kv.z;
            U[(kq + 3) * KS_STR + r] = kv.w;
            float4 vv = *(const float4*)(vinp + (size_t)(s0 + r) * 2048 + kq);
            *(float4*)&Vs[r * VS_STR + kq] = vv;
        }
        __syncthreads();

        // Step 1: S(8x4) = Q(8xk) . K(4xk)
        float sacc[8][4];
#pragma unroll
        for (int i = 0; i < 8; i++)
#pragma unroll
            for (int j = 0; j < 4; j++) sacc[i][j] = 0.f;

#pragma unroll 8
        for (int k = 0; k < 64; k++) {
            float qv[8], kv[4];
            *(float4*)(qv)     = *(const float4*)&Qs[k * QS_STR + rq];
            *(float4*)(qv + 4) = *(const float4*)&Qs[k * QS_STR + rq + 4];
            *(float4*)(kv)     = *(const float4*)&U[k * KS_STR + c4];
#pragma unroll
            for (int i = 0; i < 8; i++)
#pragma unroll
                for (int j = 0; j < 4; j++)
                    sacc[i][j] += qv[i] * kv[j];
        }
        __syncthreads();                    // done reading Ks; reuse U as St

        // Scale, causal-zero mask, write S transposed: St[s][q]
#pragma unroll
        for (int j = 0; j < 4; j++) {
            const int sg = s0 + c4 + j;
            float* strow = &U[(c4 + j) * ST_STR + rq];
#pragma unroll
            for (int i = 0; i < 8; i++) {
                const int qg = q0 + rq + i;
                strow[i] = (sg <= qg) ? sacc[i][j] * 0.125f : 0.f;
            }
        }
        __syncthreads();

        // Step 2: acc(8x4) += S(8xs) . V(s x4)
#pragma unroll 8
        for (int s = 0; s < 64; s++) {
            float sv[8], vv[4];
            *(float4*)(sv)     = *(const float4*)&U[s * ST_STR + rq];
            *(float4*)(sv + 4) = *(const float4*)&U[s * ST_STR + rq + 4];
            *(float4*)(vv)     = *(const float4*)&Vs[s * VS_STR + c4];
#pragma unroll
            for (int i = 0; i < 8; i++)
#pragma unroll
                for (int j = 0; j < 4; j++)
                    acc[i][j] += sv[i] * vv[j];
        }
    }

    // Write nudged in (b, w, c) layout: c = h*64 + n
#pragma unroll
    for (int i = 0; i < 8; i++) {
        float* op = nudged + (size_t)(b * WTOT + q0 + rq + i) * CDIM + h * HD + c4;
        *(float4*)op = make_float4(acc[i][0], acc[i][1], acc[i][2], acc[i][3]);
    }
}

// ----------------------------------------------------------------------------
// kernel_launch: proj GEMM -> fused attention -> output GEMM
// ----------------------------------------------------------------------------
extern "C" void kernel_launch(void* const* d_in, const int* in_sizes, int n_in,
                              void* d_out, int out_size)
{
    const float* x  = (const float*)d_in[0];   // (2,2048,1024)
    const float* Wp = (const float*)d_in[1];   // (2048,1024)
    const float* Wo = (const float*)d_in[2];   // (1024,1024)
    float* out = (float*)d_out;                // (2,2048,1024)

    float *all_p = nullptr, *nud_p = nullptr;
    cudaGetSymbolAddress((void**)&all_p, g_all);
    cudaGetSymbolAddress((void**)&nud_p, g_nudged);

    const int attn_smem = SM_FLOATS * (int)sizeof(float);   // 84,992 B
    cudaFuncSetAttribute(attn_kernel,
                         cudaFuncAttributeMaxDynamicSharedMemorySize, attn_smem);

    const int M = BATCH * WTOT;                 // 4096

    // 1) all = x @ W_proj^T   (4096 x 2048, K=1024)
    sgemm_abt<<<dim3(2 * CDIM / 128, M / 128), 256>>>(x, Wp, all_p, M, 2 * CDIM, CDIM);

    // 2) fused causal scores + S@V  -> nudged (b,w,c)
    attn_kernel<<<dim3(WTOT / 128, BATCH * HEADS), 256, attn_smem>>>(all_p, nud_p);

    // 3) y = nudged @ W_out^T  (4096 x 1024, K=1024)
    sgemm_abt<<<dim3(CDIM / 128, M / 128), 256>>>(nud_p, Wo, out, M, CDIM, CDIM);
}

// round 5
// speedup vs baseline: 1.5655x; 1.5655x over previous
#include <cuda_runtime.h>
#include <cuda_bf16.h>
#include <cstdint>
#include <cstddef>

#define BATCH 2
#define WTOT  2048
#define CDIM  1024
#define HEADS 16
#define MROWS 4096
#define KDIM  1024

// Scratch (no allocation allowed)
__device__ float g_all[(size_t)BATCH * WTOT * 2 * CDIM];   // 32MB proj output
__device__ float g_nudged[(size_t)MROWS * CDIM];           // 16MB attention output

// ============================================================================
// bf16 3-term split helpers.
// A-pack per k: (ah, al, ah);  B-pack per k: (bh, bh, bl)
// => per-k contribution: ah*bh + al*bh + ah*bl  (error ~ al*bl ~ 2^-16 rel)
// ============================================================================
__device__ __forceinline__ void bf3_split(float x, uint32_t& h, uint32_t& l) {
    __nv_bfloat16 bh = __float2bfloat16_rn(x);
    float hf = __bfloat162float(bh);
    __nv_bfloat16 bl = __float2bfloat16_rn(x - hf);
    h = (uint32_t)__bfloat16_as_ushort(bh);
    l = (uint32_t)__bfloat16_as_ushort(bl);
}
// pack two consecutive k values into 3 uint32 (6 bf16 slots)
__device__ __forceinline__ void packA2(float x0, float x1, uint32_t* u) {
    uint32_t h0, l0, h1, l1;
    bf3_split(x0, h0, l0); bf3_split(x1, h1, l1);
    u[0] = h0 | (l0 << 16);     // ah0, al0
    u[1] = h0 | (h1 << 16);     // ah0, ah1
    u[2] = l1 | (h1 << 16);     // al1, ah1
}
__device__ __forceinline__ void packB2(float x0, float x1, uint32_t* u) {
    uint32_t h0, l0, h1, l1;
    bf3_split(x0, h0, l0); bf3_split(x1, h1, l1);
    u[0] = h0 | (h0 << 16);     // bh0, bh0
    u[1] = l0 | (h1 << 16);     // bl0, bh1
    u[2] = h1 | (l1 << 16);     // bh1, bl1
}

// mma.sync m16n8k16 bf16 -> f32 (A row-major, B col-major)
__device__ __forceinline__ void mma16816(float* d, const uint32_t* a, const uint32_t* b) {
    asm("mma.sync.aligned.m16n8k16.row.col.f32.bf16.bf16.f32 "
        "{%0,%1,%2,%3}, {%4,%5,%6,%7}, {%8,%9}, {%0,%1,%2,%3};"
        : "+f"(d[0]), "+f"(d[1]), "+f"(d[2]), "+f"(d[3])
        : "r"(a[0]), "r"(a[1]), "r"(a[2]), "r"(a[3]), "r"(b[0]), "r"(b[1]));
}

// ============================================================================
// GEMM: C[M,N] = A[M,1024] @ B[N,1024]^T, fp32 in/out, bf16x3 internally.
// 128x128 tile, K-chunk 16 fp32 (48 bf16), double-buffered, 256 threads.
// SMEM rows padded to 56 bf16 (28 words) -> conflict-free frag loads.
// ============================================================================
#define GKC    16
#define GASTR  28                       /* words per smem row */
#define GAWRD  (128 * GASTR)            /* 3584 words per operand tile */
#define GBUFW  (2 * GAWRD)              /* A+B per buffer */
#define GSMEM  (2 * GBUFW * 4)          /* 57344 bytes */

__global__ __launch_bounds__(256, 2) void gemm_bf3(const float* __restrict__ A,
                                                   const float* __restrict__ B,
                                                   float* __restrict__ C, int N)
{
    extern __shared__ char smc[];
    uint32_t* SW = (uint32_t*)smc;
    const int tid = threadIdx.x, lane = tid & 31, wid = tid >> 5;
    const int g = lane >> 2, t = lane & 3;
    const int m0 = blockIdx.y * 128, n0 = blockIdx.x * 128;
    const int wm = wid >> 2, wn = wid & 3;     // warp tile: 64m x 32n

    const float* Ap = A + (size_t)m0 * KDIM;
    const float* Bp = B + (size_t)n0 * KDIM;

    float acc[4][4][4] = {};

    // prologue: chunk 0 -> buffer 0
    {
#pragma unroll
        for (int i = 0; i < 4; i++) {
            int idx = i * 256 + tid, rr = idx >> 3, kk = idx & 7;
            float2 ra = *(const float2*)(Ap + (size_t)rr * KDIM + 2 * kk);
            float2 rb = *(const float2*)(Bp + (size_t)rr * KDIM + 2 * kk);
            uint32_t u[3];
            int w = rr * GASTR + 3 * kk;
            packA2(ra.x, ra.y, u);
            SW[w] = u[0]; SW[w + 1] = u[1]; SW[w + 2] = u[2];
            packB2(rb.x, rb.y, u);
            SW[GAWRD + w] = u[0]; SW[GAWRD + w + 1] = u[1]; SW[GAWRD + w + 2] = u[2];
        }
    }
    __syncthreads();

    const int NCH = KDIM / GKC;   // 64
    for (int c = 0; c < NCH; c++) {
        float2 ra[4], rb[4];
        if (c + 1 < NCH) {
            const float* a = Ap + (c + 1) * GKC;
            const float* b = Bp + (c + 1) * GKC;
#pragma unroll
            for (int i = 0; i < 4; i++) {
                int idx = i * 256 + tid, rr = idx >> 3, kk = idx & 7;
                ra[i] = *(const float2*)(a + (size_t)rr * KDIM + 2 * kk);
                rb[i] = *(const float2*)(b + (size_t)rr * KDIM + 2 * kk);
            }
        }

        const uint32_t* As = SW + (c & 1) * GBUFW;
        const uint32_t* Bs = As + GAWRD;
#pragma unroll
        for (int ks = 0; ks < 3; ks++) {
            const int ko2 = ks * 8;   // word offset of this k16 step
            uint32_t af[4][4];
#pragma unroll
            for (int mf = 0; mf < 4; mf++) {
                int w0 = (wm * 64 + mf * 16 + g) * GASTR + ko2 + t;
                af[mf][0] = As[w0];
                af[mf][1] = As[w0 + 8 * GASTR];
                af[mf][2] = As[w0 + 4];
                af[mf][3] = As[w0 + 8 * GASTR + 4];
            }
            uint32_t bfr[4][2];
#pragma unroll
            for (int nf = 0; nf < 4; nf++) {
                int w0 = (wn * 32 + nf * 8 + g) * GASTR + ko2 + t;
                bfr[nf][0] = Bs[w0];
                bfr[nf][1] = Bs[w0 + 4];
            }
#pragma unroll
            for (int mf = 0; mf < 4; mf++)
#pragma unroll
                for (int nf = 0; nf < 4; nf++)
                    mma16816(acc[mf][nf], af[mf], bfr[nf]);
        }

        if (c + 1 < NCH) {
            uint32_t* Ad = SW + ((c + 1) & 1) * GBUFW;
#pragma unroll
            for (int i = 0; i < 4; i++) {
                int idx = i * 256 + tid, rr = idx >> 3, kk = idx & 7;
                uint32_t u[3];
                int w = rr * GASTR + 3 * kk;
                packA2(ra[i].x, ra[i].y, u);
                Ad[w] = u[0]; Ad[w + 1] = u[1]; Ad[w + 2] = u[2];
                packB2(rb[i].x, rb[i].y, u);
                Ad[GAWRD + w] = u[0]; Ad[GAWRD + w + 1] = u[1]; Ad[GAWRD + w + 2] = u[2];
            }
        }
        __syncthreads();
    }

    // epilogue
#pragma unroll
    for (int mf = 0; mf < 4; mf++)
#pragma unroll
        for (int nf = 0; nf < 4; nf++) {
            int row = m0 + wm * 64 + mf * 16 + g;
            int col = n0 + wn * 32 + nf * 8 + 2 * t;
            float* p = C + (size_t)row * N + col;
            *(float2*)p = make_float2(acc[mf][nf][0], acc[mf][nf][1]);
            *(float2*)(p + (size_t)8 * N) = make_float2(acc[mf][nf][2], acc[mf][nf][3]);
        }
}

// ============================================================================
// Fused causal attention (zero-mask, no softmax), bf16x3 mma version.
// CTA = (b,h, 128-q-tile), 256 threads, 8 warps.
// SMEM (bf16 units, row stride 200 = 100 words, conflict-free):
//   Q3  [128][192] A-pack     @ unit 0      (words 0)
//   K3  [ 64][192] B-pack     @ unit 25600  (words 12800)
//   V3  [ 64][192] B-pack(s)  @ unit 38400  (words 19200)  (V transposed: [n][3s+j])
//   St3 [128][192] A-pack(s)  @ unit 51200  (words 25600)
// ============================================================================
#define HSTRW 100
#define KW    12800
#define VW    19200
#define SW3   25600
#define ASMEM (76800 * 2)   /* 153600 bytes */

__global__ __launch_bounds__(256) void attn_bf3(const float* __restrict__ all,
                                                float* __restrict__ nudged)
{
    extern __shared__ char smc[];
    uint32_t* W = (uint32_t*)smc;
    __nv_bfloat16* Hb = (__nv_bfloat16*)smc;

    const int tid = threadIdx.x, lane = tid & 31, wid = tid >> 5;
    const int g = lane >> 2, t = lane & 3;
    const int q0 = blockIdx.x * 128;
    const int b = blockIdx.y >> 4, h = blockIdx.y & 15;
    const int wq = wid >> 1, wlo = wid & 1;    // 4 x 2 warp grid, 32x32 tiles

    const float* inp  = all + (size_t)b * WTOT * 2048 + h * 64;
    const float* vinp = inp + 1024;

    // pack Q tile (128 x 64) -> Q3 A-pack
#pragma unroll
    for (int i = 0; i < 16; i++) {
        int idx = i * 256 + tid, r = idx >> 5, k2 = idx & 31;
        float2 v = *(const float2*)(inp + (size_t)(q0 + r) * 2048 + 2 * k2);
        uint32_t u[3];
        int w = r * HSTRW + 3 * k2;
        packA2(v.x, v.y, u);
        W[w] = u[0]; W[w + 1] = u[1]; W[w + 2] = u[2];
    }

    float oacc[2][4][4] = {};
    const int nS = (q0 >> 6) + 2;

    for (int sb = 0; sb < nS; sb++) {
        const int s0 = sb * 64;
        __syncthreads();   // prev SV done reading V3/St3; prev QK done with K3

        // load + pack K tile (B-pack) and V tile (transposed B-pack along s)
#pragma unroll
        for (int i = 0; i < 8; i++) {
            int idx = i * 256 + tid, r = idx >> 5, k2 = idx & 31;
            float2 kv = *(const float2*)(inp + (size_t)(s0 + r) * 2048 + 2 * k2);
            uint32_t u[3];
            int w = KW + r * HSTRW + 3 * k2;
            packB2(kv.x, kv.y, u);
            W[w] = u[0]; W[w + 1] = u[1]; W[w + 2] = u[2];

            float2 vv = *(const float2*)(vinp + (size_t)(s0 + r) * 2048 + 2 * k2);
            uint32_t h0, l0, h1, l1;
            bf3_split(vv.x, h0, l0); bf3_split(vv.y, h1, l1);
            // element (s=r, n=2k2+j) -> V3[n][3r + {0,1,2}] = (vh, vh, vl)
            __nv_bfloat16* p0 = Hb + (2 * VW) + (2 * k2) * 200 + 3 * r;
            p0[0] = __ushort_as_bfloat16((uint16_t)h0);
            p0[1] = __ushort_as_bfloat16((uint16_t)h0);
            p0[2] = __ushort_as_bfloat16((uint16_t)l0);
            __nv_bfloat16* p1 = p0 + 200;
            p1[0] = __ushort_as_bfloat16((uint16_t)h1);
            p1[1] = __ushort_as_bfloat16((uint16_t)h1);
            p1[2] = __ushort_as_bfloat16((uint16_t)l1);
        }
        __syncthreads();

        // ---- QK: S[128q x 64s], warp tile 32q x 32s ----
        float sacc[2][4][4] = {};
#pragma unroll
        for (int ks = 0; ks < 12; ks++) {
            const int ko2 = ks * 8;
            uint32_t af[2][4];
#pragma unroll
            for (int mf = 0; mf < 2; mf++) {
                int w0 = (wq * 32 + mf * 16 + g) * HSTRW + ko2 + t;
                af[mf][0] = W[w0];
                af[mf][1] = W[w0 + 8 * HSTRW];
                af[mf][2] = W[w0 + 4];
                af[mf][3] = W[w0 + 8 * HSTRW + 4];
            }
            uint32_t bfr[4][2];
#pragma unroll
            for (int nf = 0; nf < 4; nf++) {
                int w0 = KW + (wlo * 32 + nf * 8 + g) * HSTRW + ko2 + t;
                bfr[nf][0] = W[w0];
                bfr[nf][1] = W[w0 + 4];
            }
#pragma unroll
            for (int mf = 0; mf < 2; mf++)
#pragma unroll
                for (int nf = 0; nf < 4; nf++)
                    mma16816(sacc[mf][nf], af[mf], bfr[nf]);
        }

        // ---- mask + scale + split -> St3 (A-pack along s) ----
#pragma unroll
        for (int mf = 0; mf < 2; mf++)
#pragma unroll
            for (int nf = 0; nf < 4; nf++) {
                const int cloc = wlo * 32 + nf * 8 + 2 * t;
                const int sg = s0 + cloc;
#pragma unroll
                for (int half = 0; half < 2; half++) {
                    const int rloc = wq * 32 + mf * 16 + g + 8 * half;
                    const int qg = q0 + rloc;
                    float v0 = (sg     <= qg) ? sacc[mf][nf][2 * half + 0] * 0.125f : 0.f;
                    float v1 = (sg + 1 <= qg) ? sacc[mf][nf][2 * half + 1] * 0.125f : 0.f;
                    uint32_t u[3];
                    packA2(v0, v1, u);
                    int w = SW3 + rloc * HSTRW + 3 * (cloc >> 1);
                    W[w] = u[0]; W[w + 1] = u[1]; W[w + 2] = u[2];
                }
            }
        __syncthreads();

        // ---- SV: O += S @ V, warp tile 32q x 32n ----
#pragma unroll
        for (int ks = 0; ks < 12; ks++) {
            const int ko2 = ks * 8;
            uint32_t af[2][4];
#pragma unroll
            for (int mf = 0; mf < 2; mf++) {
                int w0 = SW3 + (wq * 32 + mf * 16 + g) * HSTRW + ko2 + t;
                af[mf][0] = W[w0];
                af[mf][1] = W[w0 + 8 * HSTRW];
                af[mf][2] = W[w0 + 4];
                af[mf][3] = W[w0 + 8 * HSTRW + 4];
            }
            uint32_t bfr[4][2];
#pragma unroll
            for (int nf = 0; nf < 4; nf++) {
                int w0 = VW + (wlo * 32 + nf * 8 + g) * HSTRW + ko2 + t;
                bfr[nf][0] = W[w0];
                bfr[nf][1] = W[w0 + 4];
            }
#pragma unroll
            for (int mf = 0; mf < 2; mf++)
#pragma unroll
                for (int nf = 0; nf < 4; nf++)
                    mma16816(oacc[mf][nf], af[mf], bfr[nf]);
        }
    }

    // epilogue: write O in (b,w,c) layout
#pragma unroll
    for (int mf = 0; mf < 2; mf++)
#pragma unroll
        for (int nf = 0; nf < 4; nf++) {
            int row = q0 + wq * 32 + mf * 16 + g;
            int col = h * 64 + wlo * 32 + nf * 8 + 2 * t;
            float* p = nudged + (size_t)(b * WTOT + row) * CDIM + col;
            *(float2*)p = make_float2(oacc[mf][nf][0], oacc[mf][nf][1]);
            *(float2*)(p + (size_t)8 * CDIM) = make_float2(oacc[mf][nf][2], oacc[mf][nf][3]);
        }
}

// ============================================================================
// kernel_launch
// ============================================================================
extern "C" void kernel_launch(void* const* d_in, const int* in_sizes, int n_in,
                              void* d_out, int out_size)
{
    const float* x  = (const float*)d_in[0];   // (2,2048,1024)
    const float* Wp = (const float*)d_in[1];   // (2048,1024)
    const float* Wo = (const float*)d_in[2];   // (1024,1024)
    float* out = (float*)d_out;                // (2,2048,1024)

    float *all_p, *nud_p;
    cudaGetSymbolAddress((void**)&all_p, g_all);
    cudaGetSymbolAddress((void**)&nud_p, g_nudged);

    cudaFuncSetAttribute(gemm_bf3, cudaFuncAttributeMaxDynamicSharedMemorySize, GSMEM);
    cudaFuncSetAttribute(attn_bf3, cudaFuncAttributeMaxDynamicSharedMemorySize, ASMEM);

    // 1) all = x @ W_proj^T   (4096 x 2048, K=1024)
    gemm_bf3<<<dim3(2048 / 128, MROWS / 128), 256, GSMEM>>>(x, Wp, all_p, 2048);

    // 2) fused causal scores + S@V -> nudged (b,w,c)
    attn_bf3<<<dim3(WTOT / 128, BATCH * HEADS), 256, ASMEM>>>(all_p, nud_p);

    // 3) y = nudged @ W_out^T  (4096 x 1024, K=1024)
    gemm_bf3<<<dim3(CDIM / 128, MROWS / 128), 256, GSMEM>>>(nud_p, Wo, out, 1024);
}

// round 6
// speedup vs baseline: 2.0274x; 1.2950x over previous
#include <cuda_runtime.h>
#include <cuda_bf16.h>
#include <cstdint>
#include <cstddef>

#define WTOT  2048
#define CDIM  1024
#define MROWS 4096
#define KW3   1536      /* packed words per K=1024 row (3 words / 2 fp32) */
#define QW    96        /* packed words per 64-wide head row */

// ---------------- scratch (no allocation allowed) ----------------
__device__ __align__(256) float    g_v[(size_t)MROWS * CDIM];        // V fp32 staging
__device__ __align__(256) uint32_t g_xa[(size_t)MROWS * KW3];        // x A-pack
__device__ __align__(256) uint32_t g_wpb[(size_t)2048 * KW3];        // W_proj B-pack
__device__ __align__(256) uint32_t g_wob[(size_t)1024 * KW3];        // W_out B-pack
__device__ __align__(256) uint32_t g_na[(size_t)MROWS * KW3];        // nudged A-pack
__device__ __align__(256) uint32_t g_qa[(size_t)32 * 2048 * QW];     // Q A-pack per (b,h)
__device__ __align__(256) uint32_t g_kb[(size_t)32 * 2048 * QW];     // K B-pack per (b,h)
__device__ __align__(256) uint32_t g_vt[(size_t)32 * 64 * 3072];     // V^T B-pack along s

// ---------------- helpers ----------------
__device__ __forceinline__ uint32_t smem_u32(const void* p) {
    uint32_t a;
    asm("{ .reg .u64 t; cvta.to.shared.u64 t, %1; cvt.u32.u64 %0, t; }" : "=r"(a) : "l"(p));
    return a;
}
__device__ __forceinline__ void bf3_split(float x, uint32_t& h, uint32_t& l) {
    __nv_bfloat16 bh = __float2bfloat16_rn(x);
    float hf = __bfloat162float(bh);
    __nv_bfloat16 bl = __float2bfloat16_rn(x - hf);
    h = (uint32_t)__bfloat16_as_ushort(bh);
    l = (uint32_t)__bfloat16_as_ushort(bl);
}
// pack 2 consecutive k fp32 -> 6 bf16 slots (3 words)
__device__ __forceinline__ void packA2(float x0, float x1, uint32_t* u) {
    uint32_t h0, l0, h1, l1;
    bf3_split(x0, h0, l0); bf3_split(x1, h1, l1);
    u[0] = h0 | (l0 << 16); u[1] = h0 | (h1 << 16); u[2] = l1 | (h1 << 16);
}
__device__ __forceinline__ void packB2(float x0, float x1, uint32_t* u) {
    uint32_t h0, l0, h1, l1;
    bf3_split(x0, h0, l0); bf3_split(x1, h1, l1);
    u[0] = h0 | (h0 << 16); u[1] = l0 | (h1 << 16); u[2] = h1 | (l1 << 16);
}
__device__ __forceinline__ void mma16816(float* d, const uint32_t* a, const uint32_t* b) {
    asm("mma.sync.aligned.m16n8k16.row.col.f32.bf16.bf16.f32 "
        "{%0,%1,%2,%3}, {%4,%5,%6,%7}, {%8,%9}, {%0,%1,%2,%3};"
        : "+f"(d[0]), "+f"(d[1]), "+f"(d[2]), "+f"(d[3])
        : "r"(a[0]), "r"(a[1]), "r"(a[2]), "r"(a[3]), "r"(b[0]), "r"(b[1]));
}
__device__ __forceinline__ void ldsm_x4(uint32_t* r, uint32_t addr) {
    asm volatile("ldmatrix.sync.aligned.m8n8.x4.shared.b16 {%0,%1,%2,%3}, [%4];"
        : "=r"(r[0]), "=r"(r[1]), "=r"(r[2]), "=r"(r[3]) : "r"(addr));
}
__device__ __forceinline__ void cp16(uint32_t dst, const void* src) {
    asm volatile("cp.async.cg.shared.global [%0], [%1], 16;" :: "r"(dst), "l"(src) : "memory");
}
#define CP_COMMIT() asm volatile("cp.async.commit_group;" ::: "memory")
#define CP_WAIT(n)  asm volatile("cp.async.wait_group %0;" :: "n"(n) : "memory")

// ---------------- one-time pack kernels ----------------
__global__ void pack_a_k(const float* __restrict__ src, uint32_t* __restrict__ dst, int total) {
    int idx = blockIdx.x * 256 + threadIdx.x;
    if (idx >= total) return;
    int row = idx >> 9, kp = idx & 511;
    float2 v = *(const float2*)(src + (size_t)row * 1024 + 2 * kp);
    uint32_t u[3]; packA2(v.x, v.y, u);
    size_t o = (size_t)row * KW3 + 3 * kp;
    dst[o] = u[0]; dst[o + 1] = u[1]; dst[o + 2] = u[2];
}
__global__ void pack_b_k(const float* __restrict__ src, uint32_t* __restrict__ dst, int total) {
    int idx = blockIdx.x * 256 + threadIdx.x;
    if (idx >= total) return;
    int row = idx >> 9, kp = idx & 511;
    float2 v = *(const float2*)(src + (size_t)row * 1024 + 2 * kp);
    uint32_t u[3]; packB2(v.x, v.y, u);
    size_t o = (size_t)row * KW3 + 3 * kp;
    dst[o] = u[0]; dst[o + 1] = u[1]; dst[o + 2] = u[2];
}
// V transpose+pack: (b,w,c) fp32 -> VT[bh][n][3*(w/2)] B-pack along w(s)
__global__ __launch_bounds__(256) void vt_pack(const float* __restrict__ vf,
                                               uint32_t* __restrict__ vt) {
    __shared__ float smv[128][65];
    const int tid = threadIdx.x;
    const int wc = blockIdx.x, bh = blockIdx.y;
    const int b = bh >> 4, h = bh & 15;
    const int w0 = wc * 128;
    const float* src = vf + ((size_t)(b * 2048) + w0) * 1024 + h * 64;
#pragma unroll
    for (int i = 0; i < 8; i++) {
        int idx = i * 256 + tid, w = idx >> 4, c4 = (idx & 15) * 4;
        float4 v = *(const float4*)(src + (size_t)w * 1024 + c4);
        smv[w][c4] = v.x; smv[w][c4 + 1] = v.y; smv[w][c4 + 2] = v.z; smv[w][c4 + 3] = v.w;
    }
    __syncthreads();
    uint32_t* dst = vt + (size_t)bh * 64 * 3072;
#pragma unroll
    for (int i = 0; i < 16; i++) {
        int task = i * 256 + tid;
        int n = task >> 6, wp = task & 63;
        uint32_t u[3];
        packB2(smv[2 * wp][n], smv[2 * wp + 1][n], u);
        size_t o = (size_t)n * 3072 + 3 * (w0 / 2 + wp);
        dst[o] = u[0]; dst[o + 1] = u[1]; dst[o + 2] = u[2];
    }
}

// ---------------- GEMM on packed operands ----------------
// C[M,N] = A @ B^T over K=1024 (3072 bf16). 128x128 tile, chunk 32 fp32 (48 words),
// cp.async double-buffered, ldmatrix fragments, 256 thr, 8 warps (64m x 32n each).
#define STRG 52
#define CW   48
#define NCHG 32
#define ATW  (128 * STRG)
#define BUFW (2 * ATW)
#define GSMEMB (2 * BUFW * 4)      /* 106496 B */

__global__ __launch_bounds__(256, 2) void gemm_pk(
    const uint32_t* __restrict__ Ap, const uint32_t* __restrict__ Bp,
    float* __restrict__ C, int N, int mode,
    uint32_t* __restrict__ qa, uint32_t* __restrict__ kb, float* __restrict__ vf)
{
    extern __shared__ uint32_t sw[];
    const uint32_t sbase = smem_u32(sw);
    const int tid = threadIdx.x, lane = tid & 31, wid = tid >> 5;
    const int g = lane >> 2, t = lane & 3, rowInM = lane & 7, j = lane >> 3;
    const int m0 = blockIdx.y * 128, n0 = blockIdx.x * 128;
    const int wm = wid >> 2, wn = wid & 3;

    const uint32_t* Arow = Ap + (size_t)m0 * KW3;
    const uint32_t* Brow = Bp + (size_t)n0 * KW3;

#define GISSUE(c, buf) do { \
    uint32_t dA = sbase + ((buf) * BUFW) * 4; \
    uint32_t dB = dA + ATW * 4; \
    _Pragma("unroll") \
    for (int i = 0; i < 6; i++) { \
        int idx = i * 256 + tid, row = idx / 12, q = idx % 12; \
        cp16(dA + (row * STRG + q * 4) * 4, Arow + (size_t)row * KW3 + (c) * CW + q * 4); \
    } \
    _Pragma("unroll") \
    for (int i = 0; i < 6; i++) { \
        int idx = i * 256 + tid, row = idx / 12, q = idx % 12; \
        cp16(dB + (row * STRG + q * 4) * 4, Brow + (size_t)row * KW3 + (c) * CW + q * 4); \
    } \
    CP_COMMIT(); } while (0)

    GISSUE(0, 0);

    float acc[4][4][4] = {};

    for (int c = 0; c < NCHG; c++) {
        if (c + 1 < NCHG) { GISSUE(c + 1, (c + 1) & 1); CP_WAIT(1); }
        else              { CP_WAIT(0); }
        __syncthreads();
        const uint32_t abase = sbase + ((c & 1) * BUFW) * 4;
        const uint32_t bbase = abase + ATW * 4;
#pragma unroll
        for (int ks = 0; ks < 6; ks++) {
            uint32_t af[4][4], bf2[2][4];
#pragma unroll
            for (int mf = 0; mf < 4; mf++)
                ldsm_x4(af[mf], abase + ((wm * 64 + mf * 16 + rowInM + 8 * (j & 1)) * STRG
                                          + ks * 8 + 4 * (j >> 1)) * 4);
#pragma unroll
            for (int p = 0; p < 2; p++)
                ldsm_x4(bf2[p], bbase + ((wn * 32 + p * 16 + (j >> 1) * 8 + rowInM) * STRG
                                          + ks * 8 + 4 * (j & 1)) * 4);
#pragma unroll
            for (int mf = 0; mf < 4; mf++)
#pragma unroll
                for (int nf = 0; nf < 4; nf++)
                    mma16816(acc[mf][nf], af[mf], &bf2[nf >> 1][(nf & 1) * 2]);
        }
        __syncthreads();
    }

    // ---- epilogue ----
    if (mode == 0) {
#pragma unroll
        for (int mf = 0; mf < 4; mf++)
#pragma unroll
            for (int nf = 0; nf < 4; nf++) {
                int r = m0 + wm * 64 + mf * 16 + g;
                int cc = n0 + wn * 32 + nf * 8 + 2 * t;
                *(float2*)(C + (size_t)r * N + cc) =
                    make_float2(acc[mf][nf][0], acc[mf][nf][1]);
                *(float2*)(C + (size_t)(r + 8) * N + cc) =
                    make_float2(acc[mf][nf][2], acc[mf][nf][3]);
            }
    } else {
        // GEMM1: cols [0,1024) -> Q A-pack + K B-pack; cols [1024,2048) -> V fp32
#pragma unroll
        for (int mf = 0; mf < 4; mf++)
#pragma unroll
            for (int nf = 0; nf < 4; nf++) {
                int r1 = m0 + wm * 64 + mf * 16 + g;
                int cc = n0 + wn * 32 + nf * 8 + 2 * t;
                if (cc < 1024) {
                    int hh = cc >> 6, kc = cc & 63;
#pragma unroll
                    for (int half = 0; half < 2; half++) {
                        int r = r1 + 8 * half;
                        int bb = r >> 11, w = r & 2047;
                        size_t base = ((size_t)(bb * 16 + hh) * 2048 + w) * QW + 3 * (kc >> 1);
                        uint32_t u[3];
                        packA2(acc[mf][nf][2 * half], acc[mf][nf][2 * half + 1], u);
                        qa[base] = u[0]; qa[base + 1] = u[1]; qa[base + 2] = u[2];
                        packB2(acc[mf][nf][2 * half], acc[mf][nf][2 * half + 1], u);
                        kb[base] = u[0]; kb[base + 1] = u[1]; kb[base + 2] = u[2];
                    }
                } else {
                    int cv = cc - 1024;
                    *(float2*)(vf + (size_t)r1 * 1024 + cv) =
                        make_float2(acc[mf][nf][0], acc[mf][nf][1]);
                    *(float2*)(vf + (size_t)(r1 + 8) * 1024 + cv) =
                        make_float2(acc[mf][nf][2], acc[mf][nf][3]);
                }
            }
    }
#undef GISSUE
}

// ---------------- fused causal attention on packed operands ----------------
// CTA = (b,h, 128-q-tile). SMEM words: Q3[128x100] | KV x2 [ (64+64)x100 ] | St3[128x100]
#define STRA 100
#define QTW  (128 * STRA)               /* 12800 */
#define KVW  (64 * STRA)                /* 6400  */
#define STB  (QTW + 2 * 2 * KVW)        /* 38400 */
#define ASMEMB ((STB + QTW) * 4)        /* 204800 B */

__global__ __launch_bounds__(256, 1) void attn_pk(
    const uint32_t* __restrict__ qa, const uint32_t* __restrict__ kbuf,
    const uint32_t* __restrict__ vt, uint32_t* __restrict__ na)
{
    extern __shared__ uint32_t sw[];
    const uint32_t sbase = smem_u32(sw);
    const int tid = threadIdx.x, lane = tid & 31, wid = tid >> 5;
    const int g = lane >> 2, t = lane & 3, rowInM = lane & 7, j = lane >> 3;
    const int q0 = blockIdx.x * 128;
    const int bh = blockIdx.y, b = bh >> 4, h = bh & 15;
    const int wq = wid >> 1, wlo = wid & 1;

    const uint32_t* qrow = qa + ((size_t)bh * 2048 + q0) * QW;
    const uint32_t* krow = kbuf + (size_t)bh * 2048 * QW;
    const uint32_t* vrow = vt + (size_t)bh * 64 * 3072;

    // prologue: Q tile + KV block 0
#pragma unroll
    for (int i = 0; i < 12; i++) {
        int idx = i * 256 + tid, row = idx / 24, q = idx % 24;
        cp16(sbase + (row * STRA + q * 4) * 4, qrow + (size_t)row * QW + q * 4);
    }
#define KVISSUE(sb, buf) do { \
    uint32_t kdst = sbase + (QTW + (buf) * 2 * KVW) * 4; \
    uint32_t vdst = kdst + KVW * 4; \
    _Pragma("unroll") \
    for (int i = 0; i < 6; i++) { \
        int idx = i * 256 + tid, row = idx / 24, q = idx % 24; \
        cp16(kdst + (row * STRA + q * 4) * 4, krow + (size_t)((sb) * 64 + row) * QW + q * 4); \
    } \
    _Pragma("unroll") \
    for (int i = 0; i < 6; i++) { \
        int idx = i * 256 + tid, row = idx / 24, q = idx % 24; \
        cp16(vdst + (row * STRA + q * 4) * 4, vrow + (size_t)row * 3072 + (sb) * 96 + q * 4); \
    } \
    CP_COMMIT(); } while (0)

    KVISSUE(0, 0);

    float oacc[2][4][4] = {};
    const int nS = (q0 >> 6) + 2;

    for (int sb = 0; sb < nS; sb++) {
        if (sb > 0) __syncthreads();          // SV(sb-1) done with V3(buf^1)/St3
        if (sb + 1 < nS) { KVISSUE(sb + 1, (sb + 1) & 1); CP_WAIT(1); }
        else             { CP_WAIT(0); }
        __syncthreads();

        const uint32_t kbs = sbase + (QTW + (sb & 1) * 2 * KVW) * 4;
        const uint32_t vbs = kbs + KVW * 4;
        const uint32_t stb = sbase + STB * 4;

        // ---- QK ----
        float sacc[2][4][4] = {};
#pragma unroll
        for (int ks = 0; ks < 12; ks++) {
            uint32_t af[2][4], bf2[2][4];
#pragma unroll
            for (int mf = 0; mf < 2; mf++)
                ldsm_x4(af[mf], sbase + ((wq * 32 + mf * 16 + rowInM + 8 * (j & 1)) * STRA
                                          + ks * 8 + 4 * (j >> 1)) * 4);
#pragma unroll
            for (int p = 0; p < 2; p++)
                ldsm_x4(bf2[p], kbs + ((wlo * 32 + p * 16 + (j >> 1) * 8 + rowInM) * STRA
                                        + ks * 8 + 4 * (j & 1)) * 4);
#pragma unroll
            for (int mf = 0; mf < 2; mf++)
#pragma unroll
                for (int nf = 0; nf < 4; nf++)
                    mma16816(sacc[mf][nf], af[mf], &bf2[nf >> 1][(nf & 1) * 2]);
        }

        // ---- mask + scale + A-pack S -> St3 ----
        const int s0 = sb * 64;
#pragma unroll
        for (int mf = 0; mf < 2; mf++)
#pragma unroll
            for (int nf = 0; nf < 4; nf++) {
                int cloc = wlo * 32 + nf * 8 + 2 * t;
                int sg = s0 + cloc;
#pragma unroll
                for (int half = 0; half < 2; half++) {
                    int rloc = wq * 32 + mf * 16 + g + 8 * half;
                    int qg = q0 + rloc;
                    float v0 = (sg     <= qg) ? sacc[mf][nf][2 * half + 0] * 0.125f : 0.f;
                    float v1 = (sg + 1 <= qg) ? sacc[mf][nf][2 * half + 1] * 0.125f : 0.f;
                    uint32_t u[3]; packA2(v0, v1, u);
                    uint32_t w = STB + rloc * STRA + 3 * (cloc >> 1);
                    sw[w] = u[0]; sw[w + 1] = u[1]; sw[w + 2] = u[2];
                }
            }
        __syncthreads();

        // ---- SV ----
#pragma unroll
        for (int ks = 0; ks < 12; ks++) {
            uint32_t af[2][4], bf2[2][4];
#pragma unroll
            for (int mf = 0; mf < 2; mf++)
                ldsm_x4(af[mf], stb + ((wq * 32 + mf * 16 + rowInM + 8 * (j & 1)) * STRA
                                        + ks * 8 + 4 * (j >> 1)) * 4);
#pragma unroll
            for (int p = 0; p < 2; p++)
                ldsm_x4(bf2[p], vbs + ((wlo * 32 + p * 16 + (j >> 1) * 8 + rowInM) * STRA
                                        + ks * 8 + 4 * (j & 1)) * 4);
#pragma unroll
            for (int mf = 0; mf < 2; mf++)
#pragma unroll
                for (int nf = 0; nf < 4; nf++)
                    mma16816(oacc[mf][nf], af[mf], &bf2[nf >> 1][(nf & 1) * 2]);
        }
    }

    // ---- epilogue: write nudged directly as A-pack for GEMM2 ----
#pragma unroll
    for (int mf = 0; mf < 2; mf++)
#pragma unroll
        for (int nf = 0; nf < 4; nf++) {
            int cc = h * 64 + wlo * 32 + nf * 8 + 2 * t;
#pragma unroll
            for (int half = 0; half < 2; half++) {
                int row = q0 + wq * 32 + mf * 16 + g + 8 * half;
                uint32_t u[3];
                packA2(oacc[mf][nf][2 * half], oacc[mf][nf][2 * half + 1], u);
                size_t o = (size_t)(b * 2048 + row) * KW3 + 3 * (cc >> 1);
                na[o] = u[0]; na[o + 1] = u[1]; na[o + 2] = u[2];
            }
        }
#undef KVISSUE
}

// ---------------- kernel_launch ----------------
extern "C" void kernel_launch(void* const* d_in, const int* in_sizes, int n_in,
                              void* d_out, int out_size)
{
    const float* x  = (const float*)d_in[0];
    const float* Wp = (const float*)d_in[1];
    const float* Wo = (const float*)d_in[2];
    float* out = (float*)d_out;

    float* vf;
    uint32_t *xa, *wpb, *wob, *na, *qa, *kb, *vt;
    cudaGetSymbolAddress((void**)&vf,  g_v);
    cudaGetSymbolAddress((void**)&xa,  g_xa);
    cudaGetSymbolAddress((void**)&wpb, g_wpb);
    cudaGetSymbolAddress((void**)&wob, g_wob);
    cudaGetSymbolAddress((void**)&na,  g_na);
    cudaGetSymbolAddress((void**)&qa,  g_qa);
    cudaGetSymbolAddress((void**)&kb,  g_kb);
    cudaGetSymbolAddress((void**)&vt,  g_vt);

    cudaFuncSetAttribute(gemm_pk, cudaFuncAttributeMaxDynamicSharedMemorySize, GSMEMB);
    cudaFuncSetAttribute(attn_pk, cudaFuncAttributeMaxDynamicSharedMemorySize, ASMEMB);

    // one-time operand packs
    pack_a_k<<<MROWS * 512 / 256, 256>>>(x, xa, MROWS * 512);
    pack_b_k<<<2048 * 512 / 256, 256>>>(Wp, wpb, 2048 * 512);
    pack_b_k<<<1024 * 512 / 256, 256>>>(Wo, wob, 1024 * 512);

    // 1) proj GEMM; epilogue emits Q/K packs + V fp32 staging
    gemm_pk<<<dim3(2048 / 128, MROWS / 128), 256, GSMEMB>>>(
        xa, wpb, nullptr, 2048, 1, qa, kb, vf);

    // V transpose + B-pack
    vt_pack<<<dim3(WTOT / 128, 32), 256>>>(vf, vt);

    // 2) fused causal attention; epilogue emits nudged A-pack
    attn_pk<<<dim3(WTOT / 128, 32), 256, ASMEMB>>>(qa, kb, vt, na);

    // 3) output GEMM -> fp32 out
    gemm_pk<<<dim3(1024 / 128, MROWS / 128), 256, GSMEMB>>>(
        na, wob, out, 1024, 0, nullptr, nullptr, nullptr);
}

// round 7
// speedup vs baseline: 2.0977x; 1.0347x over previous
#include <cuda_runtime.h>
#include <cuda_bf16.h>
#include <cstdint>
#include <cstddef>

#define WTOT  2048
#define CDIM  1024
#define MROWS 4096
#define KW3   1536      /* packed words per K=1024 row (3 words / 2 fp32) */
#define QW    96        /* packed words per 64-wide head row */

// ---------------- scratch (no allocation allowed) ----------------
__device__ __align__(256) float    g_v[(size_t)MROWS * CDIM];        // V fp32 staging
__device__ __align__(256) uint32_t g_xa[(size_t)MROWS * KW3];        // x A-pack
__device__ __align__(256) uint32_t g_wpb[(size_t)2048 * KW3];        // W_proj B-pack
__device__ __align__(256) uint32_t g_wob[(size_t)1024 * KW3];        // W_out B-pack
__device__ __align__(256) uint32_t g_na[(size_t)MROWS * KW3];        // nudged A-pack
__device__ __align__(256) uint32_t g_qa[(size_t)32 * 2048 * QW];     // Q A-pack per (b,h)
__device__ __align__(256) uint32_t g_kb[(size_t)32 * 2048 * QW];     // K B-pack per (b,h)
__device__ __align__(256) uint32_t g_vth[(size_t)32 * 64 * 1024];    // V^T hi plane (bf16x2)
__device__ __align__(256) uint32_t g_vtl[(size_t)32 * 64 * 1024];    // V^T lo plane (bf16x2)

// ---------------- helpers ----------------
__device__ __forceinline__ uint32_t smem_u32(const void* p) {
    uint32_t a;
    asm("{ .reg .u64 t; cvta.to.shared.u64 t, %1; cvt.u32.u64 %0, t; }" : "=r"(a) : "l"(p));
    return a;
}
__device__ __forceinline__ void bf3_split(float x, uint32_t& h, uint32_t& l) {
    __nv_bfloat16 bh = __float2bfloat16_rn(x);
    float hf = __bfloat162float(bh);
    __nv_bfloat16 bl = __float2bfloat16_rn(x - hf);
    h = (uint32_t)__bfloat16_as_ushort(bh);
    l = (uint32_t)__bfloat16_as_ushort(bl);
}
__device__ __forceinline__ void packA2(float x0, float x1, uint32_t* u) {
    uint32_t h0, l0, h1, l1;
    bf3_split(x0, h0, l0); bf3_split(x1, h1, l1);
    u[0] = h0 | (l0 << 16); u[1] = h0 | (h1 << 16); u[2] = l1 | (h1 << 16);
}
__device__ __forceinline__ void packB2(float x0, float x1, uint32_t* u) {
    uint32_t h0, l0, h1, l1;
    bf3_split(x0, h0, l0); bf3_split(x1, h1, l1);
    u[0] = h0 | (h0 << 16); u[1] = l0 | (h1 << 16); u[2] = h1 | (l1 << 16);
}
// split two floats into (hi pair, lo pair) bf16x2 words
__device__ __forceinline__ void split_pair(float a, float b, uint32_t& hi, uint32_t& lo) {
    __nv_bfloat16 ah = __float2bfloat16_rn(a), bh = __float2bfloat16_rn(b);
    float af = __bfloat162float(ah), bf = __bfloat162float(bh);
    __nv_bfloat16 al = __float2bfloat16_rn(a - af), bl = __float2bfloat16_rn(b - bf);
    hi = (uint32_t)__bfloat16_as_ushort(ah) | ((uint32_t)__bfloat16_as_ushort(bh) << 16);
    lo = (uint32_t)__bfloat16_as_ushort(al) | ((uint32_t)__bfloat16_as_ushort(bl) << 16);
}
__device__ __forceinline__ void mma16816(float* d, const uint32_t* a, const uint32_t* b) {
    asm("mma.sync.aligned.m16n8k16.row.col.f32.bf16.bf16.f32 "
        "{%0,%1,%2,%3}, {%4,%5,%6,%7}, {%8,%9}, {%0,%1,%2,%3};"
        : "+f"(d[0]), "+f"(d[1]), "+f"(d[2]), "+f"(d[3])
        : "r"(a[0]), "r"(a[1]), "r"(a[2]), "r"(a[3]), "r"(b[0]), "r"(b[1]));
}
__device__ __forceinline__ void ldsm_x4(uint32_t* r, uint32_t addr) {
    asm volatile("ldmatrix.sync.aligned.m8n8.x4.shared.b16 {%0,%1,%2,%3}, [%4];"
        : "=r"(r[0]), "=r"(r[1]), "=r"(r[2]), "=r"(r[3]) : "r"(addr));
}
__device__ __forceinline__ void cp16(uint32_t dst, const void* src) {
    asm volatile("cp.async.cg.shared.global [%0], [%1], 16;" :: "r"(dst), "l"(src) : "memory");
}
#define CP_COMMIT() asm volatile("cp.async.commit_group;" ::: "memory")
#define CP_WAIT(n)  asm volatile("cp.async.wait_group %0;" :: "n"(n) : "memory")

// ---------------- one-time pack kernels ----------------
__global__ void pack_a_k(const float* __restrict__ src, uint32_t* __restrict__ dst, int total) {
    int idx = blockIdx.x * 256 + threadIdx.x;
    if (idx >= total) return;
    int row = idx >> 9, kp = idx & 511;
    float2 v = *(const float2*)(src + (size_t)row * 1024 + 2 * kp);
    uint32_t u[3]; packA2(v.x, v.y, u);
    size_t o = (size_t)row * KW3 + 3 * kp;
    dst[o] = u[0]; dst[o + 1] = u[1]; dst[o + 2] = u[2];
}
__global__ void pack_b_k(const float* __restrict__ src, uint32_t* __restrict__ dst, int total) {
    int idx = blockIdx.x * 256 + threadIdx.x;
    if (idx >= total) return;
    int row = idx >> 9, kp = idx & 511;
    float2 v = *(const float2*)(src + (size_t)row * 1024 + 2 * kp);
    uint32_t u[3]; packB2(v.x, v.y, u);
    size_t o = (size_t)row * KW3 + 3 * kp;
    dst[o] = u[0]; dst[o + 1] = u[1]; dst[o + 2] = u[2];
}
// V transpose + hi/lo bf16 planes: (b,w,c) fp32 -> vth/vtl[bh][n=64][s=2048] (bf16x2 words)
__global__ __launch_bounds__(256) void vt_pack(const float* __restrict__ vf,
                                               uint32_t* __restrict__ vth,
                                               uint32_t* __restrict__ vtl) {
    __shared__ float smv[128][65];
    const int tid = threadIdx.x;
    const int wc = blockIdx.x, bh = blockIdx.y;
    const int b = bh >> 4, h = bh & 15;
    const int w0 = wc * 128;
    const float* src = vf + ((size_t)(b * 2048) + w0) * 1024 + h * 64;
#pragma unroll
    for (int i = 0; i < 8; i++) {
        int idx = i * 256 + tid, w = idx >> 4, c4 = (idx & 15) * 4;
        float4 v = *(const float4*)(src + (size_t)w * 1024 + c4);
        smv[w][c4] = v.x; smv[w][c4 + 1] = v.y; smv[w][c4 + 2] = v.z; smv[w][c4 + 3] = v.w;
    }
    __syncthreads();
#pragma unroll
    for (int i = 0; i < 16; i++) {
        int task = i * 256 + tid;
        int n = task >> 6, wp = task & 63;
        uint32_t hi, lo;
        split_pair(smv[2 * wp][n], smv[2 * wp + 1][n], hi, lo);
        size_t o = ((size_t)bh * 64 + n) * 1024 + (w0 >> 1) + wp;
        vth[o] = hi; vtl[o] = lo;
    }
}

// ---------------- GEMM: 4-stage cp.async pipeline ----------------
// C[M,N] = A @ B^T over K=1024 (3072 bf16). 128x128 tile, chunk 16 fp32 (24 words),
// 4 SMEM stages, ONE barrier per chunk, ldmatrix fragments, 8 warps (64m x 32n).
#define STRG  28
#define CWW   24
#define NCHG  64
#define ATW28 (128 * STRG)          /* 3584 words per operand per stage */
#define STAGEW (2 * ATW28)          /* 7168 */
#define GSMEMB (4 * STAGEW * 4)     /* 114688 B */

__global__ __launch_bounds__(256, 2) void gemm_pk(
    const uint32_t* __restrict__ Ap, const uint32_t* __restrict__ Bp,
    float* __restrict__ C, int N, int mode,
    uint32_t* __restrict__ qa, uint32_t* __restrict__ kb, float* __restrict__ vf)
{
    extern __shared__ uint32_t sw[];
    const uint32_t sbase = smem_u32(sw);
    const int tid = threadIdx.x, lane = tid & 31, wid = tid >> 5;
    const int g = lane >> 2, t = lane & 3, rowInM = lane & 7, j = lane >> 3;
    const int m0 = blockIdx.y * 128, n0 = blockIdx.x * 128;
    const int wm = wid >> 2, wn = wid & 3;

    const uint32_t* Arow = Ap + (size_t)m0 * KW3;
    const uint32_t* Brow = Bp + (size_t)n0 * KW3;

#define GISSUE(c_, st_) do { \
    uint32_t base_ = sbase + (st_) * STAGEW * 4; \
    _Pragma("unroll") \
    for (int i_ = 0; i_ < 3; i_++) { \
        int idx_ = i_ * 256 + tid, row_ = idx_ / 6, q_ = idx_ % 6; \
        cp16(base_ + (row_ * STRG + q_ * 4) * 4, Arow + (size_t)row_ * KW3 + (c_) * CWW + q_ * 4); \
    } \
    _Pragma("unroll") \
    for (int i_ = 0; i_ < 3; i_++) { \
        int idx_ = i_ * 256 + tid, row_ = idx_ / 6, q_ = idx_ % 6; \
        cp16(base_ + ATW28 * 4 + (row_ * STRG + q_ * 4) * 4, \
             Brow + (size_t)row_ * KW3 + (c_) * CWW + q_ * 4); \
    } \
    CP_COMMIT(); } while (0)

    GISSUE(0, 0); GISSUE(1, 1); GISSUE(2, 2);

    float acc[4][4][4] = {};

    for (int c = 0; c < NCHG; c++) {
        const int remain = NCHG - 1 - c;
        if (remain >= 2)      CP_WAIT(2);
        else if (remain == 1) CP_WAIT(1);
        else                  CP_WAIT(0);
        __syncthreads();                       // publish chunk c + stage (c-1)&3 freed
        if (c + 3 < NCHG) GISSUE(c + 3, (c + 3) & 3);

        const uint32_t abase = sbase + (c & 3) * STAGEW * 4;
        const uint32_t bbase = abase + ATW28 * 4;
#pragma unroll
        for (int ks = 0; ks < 3; ks++) {
            uint32_t af[4][4], bf2[2][4];
#pragma unroll
            for (int mf = 0; mf < 4; mf++)
                ldsm_x4(af[mf], abase + ((wm * 64 + mf * 16 + rowInM + 8 * (j & 1)) * STRG
                                          + ks * 8 + 4 * (j >> 1)) * 4);
#pragma unroll
            for (int p = 0; p < 2; p++)
                ldsm_x4(bf2[p], bbase + ((wn * 32 + p * 16 + (j >> 1) * 8 + rowInM) * STRG
                                          + ks * 8 + 4 * (j & 1)) * 4);
#pragma unroll
            for (int mf = 0; mf < 4; mf++)
#pragma unroll
                for (int nf = 0; nf < 4; nf++)
                    mma16816(acc[mf][nf], af[mf], &bf2[nf >> 1][(nf & 1) * 2]);
        }
    }

    // ---- epilogue ----
    if (mode == 0) {
#pragma unroll
        for (int mf = 0; mf < 4; mf++)
#pragma unroll
            for (int nf = 0; nf < 4; nf++) {
                int r = m0 + wm * 64 + mf * 16 + g;
                int cc = n0 + wn * 32 + nf * 8 + 2 * t;
                *(float2*)(C + (size_t)r * N + cc) =
                    make_float2(acc[mf][nf][0], acc[mf][nf][1]);
                *(float2*)(C + (size_t)(r + 8) * N + cc) =
                    make_float2(acc[mf][nf][2], acc[mf][nf][3]);
            }
    } else {
#pragma unroll
        for (int mf = 0; mf < 4; mf++)
#pragma unroll
            for (int nf = 0; nf < 4; nf++) {
                int r1 = m0 + wm * 64 + mf * 16 + g;
                int cc = n0 + wn * 32 + nf * 8 + 2 * t;
                if (cc < 1024) {
                    int hh = cc >> 6, kc = cc & 63;
#pragma unroll
                    for (int half = 0; half < 2; half++) {
                        int r = r1 + 8 * half;
                        int bb = r >> 11, w = r & 2047;
                        size_t base = ((size_t)(bb * 16 + hh) * 2048 + w) * QW + 3 * (kc >> 1);
                        uint32_t u[3];
                        packA2(acc[mf][nf][2 * half], acc[mf][nf][2 * half + 1], u);
                        qa[base] = u[0]; qa[base + 1] = u[1]; qa[base + 2] = u[2];
                        packB2(acc[mf][nf][2 * half], acc[mf][nf][2 * half + 1], u);
                        kb[base] = u[0]; kb[base + 1] = u[1]; kb[base + 2] = u[2];
                    }
                } else {
                    int cv = cc - 1024;
                    *(float2*)(vf + (size_t)r1 * 1024 + cv) =
                        make_float2(acc[mf][nf][0], acc[mf][nf][1]);
                    *(float2*)(vf + (size_t)(r1 + 8) * 1024 + cv) =
                        make_float2(acc[mf][nf][2], acc[mf][nf][3]);
                }
            }
    }
#undef GISSUE
}

// ---------------- fused causal attention: register-direct SV ----------------
// CTA = (b,h, 128q). Warp (wq,wlo): QK tile 32q x 32s; SV accumulates partial
// O[32q x 64n] over the warp's own 32-s slice directly from QK accumulators
// (S hi/lo built in registers), V from bf16 hi/lo planes. Final cross-wlo
// reduction through SMEM once per CTA.
// SMEM words: Q[128x100] | K x2 [64x100] | V planes (bytes)
#define STRA   100
#define QTW    12800
#define KBW    6400
#define VPLANEB 9216                 /* 64 rows * 144 B */
#define VBUFB  (2 * VPLANEB)
#define VBASEB ((QTW + 2 * KBW) * 4) /* 102400 */
#define ASMEMB (VBASEB + 2 * VBUFB)  /* 139264 B */

__global__ __launch_bounds__(256, 1) void attn_pk(
    const uint32_t* __restrict__ qa, const uint32_t* __restrict__ kbuf,
    const uint32_t* __restrict__ vth, const uint32_t* __restrict__ vtl,
    uint32_t* __restrict__ na)
{
    extern __shared__ uint32_t sw[];
    const uint32_t sbase = smem_u32(sw);
    const int tid = threadIdx.x, lane = tid & 31, wid = tid >> 5;
    const int g = lane >> 2, t = lane & 3, rowInM = lane & 7, j = lane >> 3;
    const int q0 = blockIdx.x * 128;
    const int bh = blockIdx.y, b = bh >> 4, h = bh & 15;
    const int wq = wid >> 1, wlo = wid & 1;

    const uint32_t* qrow = qa + ((size_t)bh * 2048 + q0) * QW;
    const uint32_t* krow = kbuf + (size_t)bh * 2048 * QW;
    const uint32_t* vhp = vth + (size_t)bh * 64 * 1024;
    const uint32_t* vlp = vtl + (size_t)bh * 64 * 1024;

#define KVISSUE(sb_, buf_) do { \
    uint32_t kdst_ = sbase + (QTW + (buf_) * KBW) * 4; \
    _Pragma("unroll") \
    for (int i_ = 0; i_ < 6; i_++) { \
        int idx_ = i_ * 256 + tid, row_ = idx_ / 24, q_ = idx_ % 24; \
        cp16(kdst_ + (row_ * STRA + q_ * 4) * 4, \
             krow + (size_t)((sb_) * 64 + row_) * QW + q_ * 4); \
    } \
    uint32_t vdst_ = sbase + VBASEB + (buf_) * VBUFB; \
    _Pragma("unroll") \
    for (int i_ = 0; i_ < 2; i_++) { \
        int idx_ = i_ * 256 + tid, row_ = idx_ >> 3, q_ = idx_ & 7; \
        cp16(vdst_ + row_ * 144 + q_ * 16, \
             vhp + (size_t)row_ * 1024 + (sb_) * 32 + q_ * 4); \
        cp16(vdst_ + VPLANEB + row_ * 144 + q_ * 16, \
             vlp + (size_t)row_ * 1024 + (sb_) * 32 + q_ * 4); \
    } \
    CP_COMMIT(); } while (0)

    // prologue: Q tile + KV block 0 (single group)
#pragma unroll
    for (int i = 0; i < 12; i++) {
        int idx = i * 256 + tid, row = idx / 24, q = idx % 24;
        cp16(sbase + (row * STRA + q * 4) * 4, qrow + (size_t)row * QW + q * 4);
    }
    KVISSUE(0, 0);

    float oacc[2][8][4] = {};
    const int nS = (q0 >> 6) + 2;

    for (int sb = 0; sb < nS; sb++) {
        CP_WAIT(0);
        __syncthreads();                 // publish KV(sb); frees buf (sb+1)&1
        if (sb + 1 < nS) KVISSUE(sb + 1, (sb + 1) & 1);

        const uint32_t kbs = sbase + (QTW + (sb & 1) * KBW) * 4;
        const uint32_t vbs = sbase + VBASEB + (sb & 1) * VBUFB;

        // ---- QK: warp tile 32q x 32s ----
        float sacc[2][4][4] = {};
#pragma unroll
        for (int ks = 0; ks < 12; ks++) {
            uint32_t af[2][4], bf2[2][4];
#pragma unroll
            for (int mf = 0; mf < 2; mf++)
                ldsm_x4(af[mf], sbase + ((wq * 32 + mf * 16 + rowInM + 8 * (j & 1)) * STRA
                                          + ks * 8 + 4 * (j >> 1)) * 4);
#pragma unroll
            for (int p = 0; p < 2; p++)
                ldsm_x4(bf2[p], kbs + ((wlo * 32 + p * 16 + (j >> 1) * 8 + rowInM) * STRA
                                        + ks * 8 + 4 * (j & 1)) * 4);
#pragma unroll
            for (int mf = 0; mf < 2; mf++)
#pragma unroll
                for (int nf = 0; nf < 4; nf++)
                    mma16816(sacc[mf][nf], af[mf], &bf2[nf >> 1][(nf & 1) * 2]);
        }

        // ---- mask + scale in registers ----
        const int s0 = sb * 64 + wlo * 32;
#pragma unroll
        for (int mf = 0; mf < 2; mf++)
#pragma unroll
            for (int nf = 0; nf < 4; nf++)
#pragma unroll
                for (int e = 0; e < 4; e++) {
                    int sg = s0 + nf * 8 + 2 * t + (e & 1);
                    int qg = q0 + wq * 32 + mf * 16 + g + 8 * (e >> 1);
                    sacc[mf][nf][e] = (sg <= qg) ? sacc[mf][nf][e] * 0.125f : 0.f;
                }

        // ---- SV: A frags straight from sacc (hi/lo), B from V planes ----
#pragma unroll
        for (int ki = 0; ki < 2; ki++) {
            uint32_t ash[2][4], asl[2][4];
#pragma unroll
            for (int mf = 0; mf < 2; mf++) {
                split_pair(sacc[mf][2 * ki][0],     sacc[mf][2 * ki][1],     ash[mf][0], asl[mf][0]);
                split_pair(sacc[mf][2 * ki][2],     sacc[mf][2 * ki][3],     ash[mf][1], asl[mf][1]);
                split_pair(sacc[mf][2 * ki + 1][0], sacc[mf][2 * ki + 1][1], ash[mf][2], asl[mf][2]);
                split_pair(sacc[mf][2 * ki + 1][2], sacc[mf][2 * ki + 1][3], ash[mf][3], asl[mf][3]);
            }
            uint32_t bh_[4][4], bl_[4][4];
#pragma unroll
            for (int p = 0; p < 4; p++) {
                uint32_t col = wlo * 64 + ki * 32 + (j & 1) * 16;
                uint32_t row = (p * 16 + (j >> 1) * 8 + rowInM) * 144;
                ldsm_x4(bh_[p], vbs + row + col);
                ldsm_x4(bl_[p], vbs + VPLANEB + row + col);
            }
#pragma unroll
            for (int mf = 0; mf < 2; mf++)
#pragma unroll
                for (int nf = 0; nf < 8; nf++) {
                    const uint32_t* bhf = &bh_[nf >> 1][(nf & 1) * 2];
                    const uint32_t* blf = &bl_[nf >> 1][(nf & 1) * 2];
                    mma16816(oacc[mf][nf], ash[mf], bhf);
                    mma16816(oacc[mf][nf], asl[mf], bhf);
                    mma16816(oacc[mf][nf], ash[mf], blf);
                }
        }
    }

    // ---- cross-wlo reduction (scratch over Q area, stride 66) ----
    __syncthreads();
    if (wlo == 1) {
#pragma unroll
        for (int mf = 0; mf < 2; mf++)
#pragma unroll
            for (int nf = 0; nf < 8; nf++)
#pragma unroll
                for (int e = 0; e < 4; e++) {
                    int qloc = mf * 16 + g + 8 * (e >> 1);
                    int n = nf * 8 + 2 * t + (e & 1);
                    sw[wq * 2112 + qloc * 66 + n] = __float_as_uint(oacc[mf][nf][e]);
                }
    }
    __syncthreads();
    if (wlo == 0) {
#pragma unroll
        for (int mf = 0; mf < 2; mf++)
#pragma unroll
            for (int nf = 0; nf < 8; nf++)
#pragma unroll
                for (int half = 0; half < 2; half++) {
                    int qloc = mf * 16 + g + 8 * half;
                    int n = nf * 8 + 2 * t;
                    float sA = oacc[mf][nf][2 * half] +
                               __uint_as_float(sw[wq * 2112 + qloc * 66 + n]);
                    float sB = oacc[mf][nf][2 * half + 1] +
                               __uint_as_float(sw[wq * 2112 + qloc * 66 + n + 1]);
                    uint32_t u[3]; packA2(sA, sB, u);
                    int row = q0 + wq * 32 + qloc;
                    int cc = h * 64 + n;
                    size_t o = (size_t)(b * 2048 + row) * KW3 + 3 * (cc >> 1);
                    na[o] = u[0]; na[o + 1] = u[1]; na[o + 2] = u[2];
                }
    }
#undef KVISSUE
}

// ---------------- kernel_launch ----------------
extern "C" void kernel_launch(void* const* d_in, const int* in_sizes, int n_in,
                              void* d_out, int out_size)
{
    const float* x  = (const float*)d_in[0];
    const float* Wp = (const float*)d_in[1];
    const float* Wo = (const float*)d_in[2];
    float* out = (float*)d_out;

    float* vf;
    uint32_t *xa, *wpb, *wob, *na, *qa, *kb, *vth, *vtl;
    cudaGetSymbolAddress((void**)&vf,  g_v);
    cudaGetSymbolAddress((void**)&xa,  g_xa);
    cudaGetSymbolAddress((void**)&wpb, g_wpb);
    cudaGetSymbolAddress((void**)&wob, g_wob);
    cudaGetSymbolAddress((void**)&na,  g_na);
    cudaGetSymbolAddress((void**)&qa,  g_qa);
    cudaGetSymbolAddress((void**)&kb,  g_kb);
    cudaGetSymbolAddress((void**)&vth, g_vth);
    cudaGetSymbolAddress((void**)&vtl, g_vtl);

    cudaFuncSetAttribute(gemm_pk, cudaFuncAttributeMaxDynamicSharedMemorySize, GSMEMB);
    cudaFuncSetAttribute(attn_pk, cudaFuncAttributeMaxDynamicSharedMemorySize, ASMEMB);

    pack_a_k<<<MROWS * 512 / 256, 256>>>(x, xa, MROWS * 512);
    pack_b_k<<<2048 * 512 / 256, 256>>>(Wp, wpb, 2048 * 512);
    pack_b_k<<<1024 * 512 / 256, 256>>>(Wo, wob, 1024 * 512);

    // 1) proj GEMM; epilogue emits Q/K packs + V fp32 staging
    gemm_pk<<<dim3(2048 / 128, MROWS / 128), 256, GSMEMB>>>(
        xa, wpb, nullptr, 2048, 1, qa, kb, vf);

    // V transpose -> hi/lo bf16 planes
    vt_pack<<<dim3(WTOT / 128, 32), 256>>>(vf, vth, vtl);

    // 2) fused causal attention; epilogue emits nudged A-pack
    attn_pk<<<dim3(WTOT / 128, 32), 256, ASMEMB>>>(qa, kb, vth, vtl, na);

    // 3) output GEMM -> fp32 out
    gemm_pk<<<dim3(1024 / 128, MROWS / 128), 256, GSMEMB>>>(
        na, wob, out, 1024, 0, nullptr, nullptr, nullptr);
}

// round 8
// speedup vs baseline: 2.2779x; 1.0859x over previous
#include <cuda_runtime.h>
#include <cuda_bf16.h>
#include <cstdint>
#include <cstddef>

#define WTOT  2048
#define CDIM  1024
#define MROWS 4096
#define KW3   1536      /* packed words per K=1024 row (3 words / 2 fp32) */
#define QW    96        /* packed words per 64-wide head row */

// ---------------- scratch (no allocation allowed) ----------------
__device__ __align__(256) float    g_v[(size_t)MROWS * CDIM];        // V fp32 staging
__device__ __align__(256) uint32_t g_xa[(size_t)MROWS * KW3];        // x A-pack
__device__ __align__(256) uint32_t g_wpb[(size_t)2048 * KW3];        // W_proj B-pack
__device__ __align__(256) uint32_t g_wob[(size_t)1024 * KW3];        // W_out B-pack
__device__ __align__(256) uint32_t g_na[(size_t)MROWS * KW3];        // nudged A-pack
__device__ __align__(256) uint32_t g_qa[(size_t)32 * 2048 * QW];     // Q A-pack per (b,h)
__device__ __align__(256) uint32_t g_kb[(size_t)32 * 2048 * QW];     // K B-pack per (b,h)
__device__ __align__(256) uint32_t g_vth[(size_t)32 * 64 * 1024];    // V^T hi plane (bf16x2)
__device__ __align__(256) uint32_t g_vtl[(size_t)32 * 64 * 1024];    // V^T lo plane (bf16x2)

// ---------------- helpers ----------------
__device__ __forceinline__ uint32_t smem_u32(const void* p) {
    uint32_t a;
    asm("{ .reg .u64 t; cvta.to.shared.u64 t, %1; cvt.u32.u64 %0, t; }" : "=r"(a) : "l"(p));
    return a;
}
__device__ __forceinline__ void bf3_split(float x, uint32_t& h, uint32_t& l) {
    __nv_bfloat16 bh = __float2bfloat16_rn(x);
    float hf = __bfloat162float(bh);
    __nv_bfloat16 bl = __float2bfloat16_rn(x - hf);
    h = (uint32_t)__bfloat16_as_ushort(bh);
    l = (uint32_t)__bfloat16_as_ushort(bl);
}
__device__ __forceinline__ void packA2(float x0, float x1, uint32_t* u) {
    uint32_t h0, l0, h1, l1;
    bf3_split(x0, h0, l0); bf3_split(x1, h1, l1);
    u[0] = h0 | (l0 << 16); u[1] = h0 | (h1 << 16); u[2] = l1 | (h1 << 16);
}
__device__ __forceinline__ void packB2(float x0, float x1, uint32_t* u) {
    uint32_t h0, l0, h1, l1;
    bf3_split(x0, h0, l0); bf3_split(x1, h1, l1);
    u[0] = h0 | (h0 << 16); u[1] = l0 | (h1 << 16); u[2] = h1 | (l1 << 16);
}
__device__ __forceinline__ void split_pair(float a, float b, uint32_t& hi, uint32_t& lo) {
    __nv_bfloat16 ah = __float2bfloat16_rn(a), bh = __float2bfloat16_rn(b);
    float af = __bfloat162float(ah), bf = __bfloat162float(bh);
    __nv_bfloat16 al = __float2bfloat16_rn(a - af), bl = __float2bfloat16_rn(b - bf);
    hi = (uint32_t)__bfloat16_as_ushort(ah) | ((uint32_t)__bfloat16_as_ushort(bh) << 16);
    lo = (uint32_t)__bfloat16_as_ushort(al) | ((uint32_t)__bfloat16_as_ushort(bl) << 16);
}
__device__ __forceinline__ void mma16816(float* d, const uint32_t* a, const uint32_t* b) {
    asm("mma.sync.aligned.m16n8k16.row.col.f32.bf16.bf16.f32 "
        "{%0,%1,%2,%3}, {%4,%5,%6,%7}, {%8,%9}, {%0,%1,%2,%3};"
        : "+f"(d[0]), "+f"(d[1]), "+f"(d[2]), "+f"(d[3])
        : "r"(a[0]), "r"(a[1]), "r"(a[2]), "r"(a[3]), "r"(b[0]), "r"(b[1]));
}
__device__ __forceinline__ void ldsm_x4(uint32_t* r, uint32_t addr) {
    asm volatile("ldmatrix.sync.aligned.m8n8.x4.shared.b16 {%0,%1,%2,%3}, [%4];"
        : "=r"(r[0]), "=r"(r[1]), "=r"(r[2]), "=r"(r[3]) : "r"(addr));
}
__device__ __forceinline__ void cp16(uint32_t dst, const void* src) {
    asm volatile("cp.async.cg.shared.global [%0], [%1], 16;" :: "r"(dst), "l"(src) : "memory");
}
#define CP_COMMIT() asm volatile("cp.async.commit_group;" ::: "memory")
#define CP_WAIT(n)  asm volatile("cp.async.wait_group %0;" :: "n"(n) : "memory")

// ---------------- one fused one-time pack kernel ----------------
// tasks: [0, 2M)   : x -> g_xa (A-pack)
//        [2M, 3M)  : W_proj -> g_wpb (B-pack)
//        [3M, 3.5M): W_out -> g_wob (B-pack)
#define NTASK_X  (MROWS * 512)
#define NTASK_WP (2048 * 512)
#define NTASK_WO (1024 * 512)
__global__ void pack_all(const float* __restrict__ x, const float* __restrict__ Wp,
                         const float* __restrict__ Wo,
                         uint32_t* __restrict__ xa, uint32_t* __restrict__ wpb,
                         uint32_t* __restrict__ wob) {
    int idx = blockIdx.x * 256 + threadIdx.x;
    const float* src; uint32_t* dst; int aform;
    if (idx < NTASK_X)                   { src = x;  dst = xa;  aform = 1; }
    else if (idx < NTASK_X + NTASK_WP)   { src = Wp; dst = wpb; aform = 0; idx -= NTASK_X; }
    else if (idx < NTASK_X + NTASK_WP + NTASK_WO)
                                         { src = Wo; dst = wob; aform = 0; idx -= NTASK_X + NTASK_WP; }
    else return;
    int row = idx >> 9, kp = idx & 511;
    float2 v = *(const float2*)(src + (size_t)row * 1024 + 2 * kp);
    uint32_t u[3];
    if (aform) packA2(v.x, v.y, u); else packB2(v.x, v.y, u);
    size_t o = (size_t)row * KW3 + 3 * kp;
    dst[o] = u[0]; dst[o + 1] = u[1]; dst[o + 2] = u[2];
}

// V transpose + hi/lo bf16 planes: (b,w,c) fp32 -> vth/vtl[bh][n=64][s/2=1024] (bf16x2)
__global__ __launch_bounds__(256) void vt_pack(const float* __restrict__ vf,
                                               uint32_t* __restrict__ vth,
                                               uint32_t* __restrict__ vtl) {
    __shared__ float smv[128][65];
    const int tid = threadIdx.x;
    const int wc = blockIdx.x, bh = blockIdx.y;
    const int b = bh >> 4, h = bh & 15;
    const int w0 = wc * 128;
    const float* src = vf + ((size_t)(b * 2048) + w0) * 1024 + h * 64;
#pragma unroll
    for (int i = 0; i < 8; i++) {
        int idx = i * 256 + tid, w = idx >> 4, c4 = (idx & 15) * 4;
        float4 v = *(const float4*)(src + (size_t)w * 1024 + c4);
        smv[w][c4] = v.x; smv[w][c4 + 1] = v.y; smv[w][c4 + 2] = v.z; smv[w][c4 + 3] = v.w;
    }
    __syncthreads();
#pragma unroll
    for (int i = 0; i < 16; i++) {
        int task = i * 256 + tid;
        int n = task >> 6, wp = task & 63;
        uint32_t hi, lo;
        split_pair(smv[2 * wp][n], smv[2 * wp + 1][n], hi, lo);
        size_t o = ((size_t)bh * 64 + n) * 1024 + (w0 >> 1) + wp;
        vth[o] = hi; vtl[o] = lo;
    }
}

// ---------------- GEMM: chunk-32, 2-stage, ONE barrier per chunk ----------------
// C[M,N] = A @ B^T over K=1024 (3072 bf16). 128x128 tile, chunk 32 fp32 (48 words),
// ldmatrix fragments, 8 warps (64m x 32n each).
#define STRG 52
#define CW   48
#define NCHG 32
#define ATW  (128 * STRG)           /* 6656 words per operand */
#define BUFW (2 * ATW)              /* 13312 */
#define GSMEMB (2 * BUFW * 4)       /* 106496 B */

__global__ __launch_bounds__(256, 2) void gemm_pk(
    const uint32_t* __restrict__ Ap, const uint32_t* __restrict__ Bp,
    float* __restrict__ C, int N, int mode,
    uint32_t* __restrict__ qa, uint32_t* __restrict__ kb, float* __restrict__ vf)
{
    extern __shared__ uint32_t sw[];
    const uint32_t sbase = smem_u32(sw);
    const int tid = threadIdx.x, lane = tid & 31, wid = tid >> 5;
    const int g = lane >> 2, t = lane & 3, rowInM = lane & 7, j = lane >> 3;
    const int m0 = blockIdx.y * 128, n0 = blockIdx.x * 128;
    const int wm = wid >> 2, wn = wid & 3;

    const uint32_t* Arow = Ap + (size_t)m0 * KW3;
    const uint32_t* Brow = Bp + (size_t)n0 * KW3;

#define GISSUE(c_, buf_) do { \
    uint32_t dA_ = sbase + (buf_) * BUFW * 4; \
    uint32_t dB_ = dA_ + ATW * 4; \
    _Pragma("unroll") \
    for (int i_ = 0; i_ < 6; i_++) { \
        int idx_ = i_ * 256 + tid, row_ = idx_ / 12, q_ = idx_ % 12; \
        cp16(dA_ + (row_ * STRG + q_ * 4) * 4, Arow + (size_t)row_ * KW3 + (c_) * CW + q_ * 4); \
    } \
    _Pragma("unroll") \
    for (int i_ = 0; i_ < 6; i_++) { \
        int idx_ = i_ * 256 + tid, row_ = idx_ / 12, q_ = idx_ % 12; \
        cp16(dB_ + (row_ * STRG + q_ * 4) * 4, Brow + (size_t)row_ * KW3 + (c_) * CW + q_ * 4); \
    } \
    CP_COMMIT(); } while (0)

    GISSUE(0, 0);

    float acc[4][4][4] = {};

    for (int c = 0; c < NCHG; c++) {
        CP_WAIT(0);
        __syncthreads();                 // publish chunk c; stage (c+1)&1 is free
        if (c + 1 < NCHG) GISSUE(c + 1, (c + 1) & 1);

        const uint32_t abase = sbase + (c & 1) * BUFW * 4;
        const uint32_t bbase = abase + ATW * 4;
#pragma unroll
        for (int ks = 0; ks < 6; ks++) {
            uint32_t af[4][4], bf2[2][4];
#pragma unroll
            for (int mf = 0; mf < 4; mf++)
                ldsm_x4(af[mf], abase + ((wm * 64 + mf * 16 + rowInM + 8 * (j & 1)) * STRG
                                          + ks * 8 + 4 * (j >> 1)) * 4);
#pragma unroll
            for (int p = 0; p < 2; p++)
                ldsm_x4(bf2[p], bbase + ((wn * 32 + p * 16 + (j >> 1) * 8 + rowInM) * STRG
                                          + ks * 8 + 4 * (j & 1)) * 4);
#pragma unroll
            for (int mf = 0; mf < 4; mf++)
#pragma unroll
                for (int nf = 0; nf < 4; nf++)
                    mma16816(acc[mf][nf], af[mf], &bf2[nf >> 1][(nf & 1) * 2]);
        }
    }

    // ---- epilogue ----
    if (mode == 0) {
#pragma unroll
        for (int mf = 0; mf < 4; mf++)
#pragma unroll
            for (int nf = 0; nf < 4; nf++) {
                int r = m0 + wm * 64 + mf * 16 + g;
                int cc = n0 + wn * 32 + nf * 8 + 2 * t;
                *(float2*)(C + (size_t)r * N + cc) =
                    make_float2(acc[mf][nf][0], acc[mf][nf][1]);
                *(float2*)(C + (size_t)(r + 8) * N + cc) =
                    make_float2(acc[mf][nf][2], acc[mf][nf][3]);
            }
    } else {
        // GEMM1: cols [0,1024) -> Q A-pack + K B-pack; cols [1024,2048) -> V fp32
#pragma unroll
        for (int mf = 0; mf < 4; mf++)
#pragma unroll
            for (int nf = 0; nf < 4; nf++) {
                int r1 = m0 + wm * 64 + mf * 16 + g;
                int cc = n0 + wn * 32 + nf * 8 + 2 * t;
                if (cc < 1024) {
                    int hh = cc >> 6, kc = cc & 63;
#pragma unroll
                    for (int half = 0; half < 2; half++) {
                        int r = r1 + 8 * half;
                        int bb = r >> 11, w = r & 2047;
                        size_t base = ((size_t)(bb * 16 + hh) * 2048 + w) * QW + 3 * (kc >> 1);
                        uint32_t u[3];
                        packA2(acc[mf][nf][2 * half], acc[mf][nf][2 * half + 1], u);
                        qa[base] = u[0]; qa[base + 1] = u[1]; qa[base + 2] = u[2];
                        packB2(acc[mf][nf][2 * half], acc[mf][nf][2 * half + 1], u);
                        kb[base] = u[0]; kb[base + 1] = u[1]; kb[base + 2] = u[2];
                    }
                } else {
                    int cv = cc - 1024;
                    *(float2*)(vf + (size_t)r1 * 1024 + cv) =
                        make_float2(acc[mf][nf][0], acc[mf][nf][1]);
                    *(float2*)(vf + (size_t)(r1 + 8) * 1024 + cv) =
                        make_float2(acc[mf][nf][2], acc[mf][nf][3]);
                }
            }
    }
#undef GISSUE
}

// ---------------- fused causal attention: register-direct SV (R7, unchanged) --
#define STRA   100
#define QTW    12800
#define KBW    6400
#define VPLANEB 9216                 /* 64 rows * 144 B */
#define VBUFB  (2 * VPLANEB)
#define VBASEB ((QTW + 2 * KBW) * 4) /* 102400 */
#define ASMEMB (VBASEB + 2 * VBUFB)  /* 139264 B */

__global__ __launch_bounds__(256, 1) void attn_pk(
    const uint32_t* __restrict__ qa, const uint32_t* __restrict__ kbuf,
    const uint32_t* __restrict__ vth, const uint32_t* __restrict__ vtl,
    uint32_t* __restrict__ na)
{
    extern __shared__ uint32_t sw[];
    const uint32_t sbase = smem_u32(sw);
    const int tid = threadIdx.x, lane = tid & 31, wid = tid >> 5;
    const int g = lane >> 2, t = lane & 3, rowInM = lane & 7, j = lane >> 3;
    const int q0 = blockIdx.x * 128;
    const int bh = blockIdx.y, b = bh >> 4, h = bh & 15;
    const int wq = wid >> 1, wlo = wid & 1;

    const uint32_t* qrow = qa + ((size_t)bh * 2048 + q0) * QW;
    const uint32_t* krow = kbuf + (size_t)bh * 2048 * QW;
    const uint32_t* vhp = vth + (size_t)bh * 64 * 1024;
    const uint32_t* vlp = vtl + (size_t)bh * 64 * 1024;

#define KVISSUE(sb_, buf_) do { \
    uint32_t kdst_ = sbase + (QTW + (buf_) * KBW) * 4; \
    _Pragma("unroll") \
    for (int i_ = 0; i_ < 6; i_++) { \
        int idx_ = i_ * 256 + tid, row_ = idx_ / 24, q_ = idx_ % 24; \
        cp16(kdst_ + (row_ * STRA + q_ * 4) * 4, \
             krow + (size_t)((sb_) * 64 + row_) * QW + q_ * 4); \
    } \
    uint32_t vdst_ = sbase + VBASEB + (buf_) * VBUFB; \
    _Pragma("unroll") \
    for (int i_ = 0; i_ < 2; i_++) { \
        int idx_ = i_ * 256 + tid, row_ = idx_ >> 3, q_ = idx_ & 7; \
        cp16(vdst_ + row_ * 144 + q_ * 16, \
             vhp + (size_t)row_ * 1024 + (sb_) * 32 + q_ * 4); \
        cp16(vdst_ + VPLANEB + row_ * 144 + q_ * 16, \
             vlp + (size_t)row_ * 1024 + (sb_) * 32 + q_ * 4); \
    } \
    CP_COMMIT(); } while (0)

#pragma unroll
    for (int i = 0; i < 12; i++) {
        int idx = i * 256 + tid, row = idx / 24, q = idx % 24;
        cp16(sbase + (row * STRA + q * 4) * 4, qrow + (size_t)row * QW + q * 4);
    }
    KVISSUE(0, 0);

    float oacc[2][8][4] = {};
    const int nS = (q0 >> 6) + 2;

    for (int sb = 0; sb < nS; sb++) {
        CP_WAIT(0);
        __syncthreads();
        if (sb + 1 < nS) KVISSUE(sb + 1, (sb + 1) & 1);

        const uint32_t kbs = sbase + (QTW + (sb & 1) * KBW) * 4;
        const uint32_t vbs = sbase + VBASEB + (sb & 1) * VBUFB;

        // ---- QK ----
        float sacc[2][4][4] = {};
#pragma unroll
        for (int ks = 0; ks < 12; ks++) {
            uint32_t af[2][4], bf2[2][4];
#pragma unroll
            for (int mf = 0; mf < 2; mf++)
                ldsm_x4(af[mf], sbase + ((wq * 32 + mf * 16 + rowInM + 8 * (j & 1)) * STRA
                                          + ks * 8 + 4 * (j >> 1)) * 4);
#pragma unroll
            for (int p = 0; p < 2; p++)
                ldsm_x4(bf2[p], kbs + ((wlo * 32 + p * 16 + (j >> 1) * 8 + rowInM) * STRA
                                        + ks * 8 + 4 * (j & 1)) * 4);
#pragma unroll
            for (int mf = 0; mf < 2; mf++)
#pragma unroll
                for (int nf = 0; nf < 4; nf++)
                    mma16816(sacc[mf][nf], af[mf], &bf2[nf >> 1][(nf & 1) * 2]);
        }

        // ---- mask + scale ----
        const int s0 = sb * 64 + wlo * 32;
#pragma unroll
        for (int mf = 0; mf < 2; mf++)
#pragma unroll
            for (int nf = 0; nf < 4; nf++)
#pragma unroll
                for (int e = 0; e < 4; e++) {
                    int sg = s0 + nf * 8 + 2 * t + (e & 1);
                    int qg = q0 + wq * 32 + mf * 16 + g + 8 * (e >> 1);
                    sacc[mf][nf][e] = (sg <= qg) ? sacc[mf][nf][e] * 0.125f : 0.f;
                }

        // ---- SV ----
#pragma unroll
        for (int ki = 0; ki < 2; ki++) {
            uint32_t ash[2][4], asl[2][4];
#pragma unroll
            for (int mf = 0; mf < 2; mf++) {
                split_pair(sacc[mf][2 * ki][0],     sacc[mf][2 * ki][1],     ash[mf][0], asl[mf][0]);
                split_pair(sacc[mf][2 * ki][2],     sacc[mf][2 * ki][3],     ash[mf][1], asl[mf][1]);
                split_pair(sacc[mf][2 * ki + 1][0], sacc[mf][2 * ki + 1][1], ash[mf][2], asl[mf][2]);
                split_pair(sacc[mf][2 * ki + 1][2], sacc[mf][2 * ki + 1][3], ash[mf][3], asl[mf][3]);
            }
            uint32_t bh_[4][4], bl_[4][4];
#pragma unroll
            for (int p = 0; p < 4; p++) {
                uint32_t col = wlo * 64 + ki * 32 + (j & 1) * 16;
                uint32_t row = (p * 16 + (j >> 1) * 8 + rowInM) * 144;
                ldsm_x4(bh_[p], vbs + row + col);
                ldsm_x4(bl_[p], vbs + VPLANEB + row + col);
            }
#pragma unroll
            for (int mf = 0; mf < 2; mf++)
#pragma unroll
                for (int nf = 0; nf < 8; nf++) {
                    const uint32_t* bhf = &bh_[nf >> 1][(nf & 1) * 2];
                    const uint32_t* blf = &bl_[nf >> 1][(nf & 1) * 2];
                    mma16816(oacc[mf][nf], ash[mf], bhf);
                    mma16816(oacc[mf][nf], asl[mf], bhf);
                    mma16816(oacc[mf][nf], ash[mf], blf);
                }
        }
    }

    // ---- cross-wlo reduction ----
    __syncthreads();
    if (wlo == 1) {
#pragma unroll
        for (int mf = 0; mf < 2; mf++)
#pragma unroll
            for (int nf = 0; nf < 8; nf++)
#pragma unroll
                for (int e = 0; e < 4; e++) {
                    int qloc = mf * 16 + g + 8 * (e >> 1);
                    int n = nf * 8 + 2 * t + (e & 1);
                    sw[wq * 2112 + qloc * 66 + n] = __float_as_uint(oacc[mf][nf][e]);
                }
    }
    __syncthreads();
    if (wlo == 0) {
#pragma unroll
        for (int mf = 0; mf < 2; mf++)
#pragma unroll
            for (int nf = 0; nf < 8; nf++)
#pragma unroll
                for (int half = 0; half < 2; half++) {
                    int qloc = mf * 16 + g + 8 * half;
                    int n = nf * 8 + 2 * t;
                    float sA = oacc[mf][nf][2 * half] +
                               __uint_as_float(sw[wq * 2112 + qloc * 66 + n]);
                    float sB = oacc[mf][nf][2 * half + 1] +
                               __uint_as_float(sw[wq * 2112 + qloc * 66 + n + 1]);
                    uint32_t u[3]; packA2(sA, sB, u);
                    int row = q0 + wq * 32 + qloc;
                    int cc = h * 64 + n;
                    size_t o = (size_t)(b * 2048 + row) * KW3 + 3 * (cc >> 1);
                    na[o] = u[0]; na[o + 1] = u[1]; na[o + 2] = u[2];
                }
    }
#undef KVISSUE
}

// ---------------- kernel_launch ----------------
extern "C" void kernel_launch(void* const* d_in, const int* in_sizes, int n_in,
                              void* d_out, int out_size)
{
    const float* x  = (const float*)d_in[0];
    const float* Wp = (const float*)d_in[1];
    const float* Wo = (const float*)d_in[2];
    float* out = (float*)d_out;

    float* vf;
    uint32_t *xa, *wpb, *wob, *na, *qa, *kb, *vth, *vtl;
    cudaGetSymbolAddress((void**)&vf,  g_v);
    cudaGetSymbolAddress((void**)&xa,  g_xa);
    cudaGetSymbolAddress((void**)&wpb, g_wpb);
    cudaGetSymbolAddress((void**)&wob, g_wob);
    cudaGetSymbolAddress((void**)&na,  g_na);
    cudaGetSymbolAddress((void**)&qa,  g_qa);
    cudaGetSymbolAddress((void**)&kb,  g_kb);
    cudaGetSymbolAddress((void**)&vth, g_vth);
    cudaGetSymbolAddress((void**)&vtl, g_vtl);

    cudaFuncSetAttribute(gemm_pk, cudaFuncAttributeMaxDynamicSharedMemorySize, GSMEMB);
    cudaFuncSetAttribute(attn_pk, cudaFuncAttributeMaxDynamicSharedMemorySize, ASMEMB);

    // fused one-time operand packs
    {
        int total = NTASK_X + NTASK_WP + NTASK_WO;
        pack_all<<<(total + 255) / 256, 256>>>(x, Wp, Wo, xa, wpb, wob);
    }

    // 1) proj GEMM; epilogue emits Q/K packs + V fp32 staging
    gemm_pk<<<dim3(2048 / 128, MROWS / 128), 256, GSMEMB>>>(
        xa, wpb, nullptr, 2048, 1, qa, kb, vf);

    // V transpose -> hi/lo bf16 planes
    vt_pack<<<dim3(WTOT / 128, 32), 256>>>(vf, vth, vtl);

    // 2) fused causal attention; epilogue emits nudged A-pack
    attn_pk<<<dim3(WTOT / 128, 32), 256, ASMEMB>>>(qa, kb, vth, vtl, na);

    // 3) output GEMM -> fp32 out
    gemm_pk<<<dim3(1024 / 128, MROWS / 128), 256, GSMEMB>>>(
        na, wob, out, 1024, 0, nullptr, nullptr, nullptr);
}

// round 9
// speedup vs baseline: 2.4241x; 1.0642x over previous
#include <cuda_runtime.h>
#include <cuda_bf16.h>
#include <cstdint>
#include <cstddef>

#define WTOT  2048
#define CDIM  1024
#define MROWS 4096
#define KW3   1536      /* packed words per K=1024 row (3 words / 2 fp32) */
#define QW    96        /* packed words per 64-wide head row */

// ---------------- scratch (no allocation allowed) ----------------
__device__ __align__(256) float    g_v[(size_t)MROWS * CDIM];        // V fp32 staging
__device__ __align__(256) uint32_t g_xa[(size_t)MROWS * KW3];        // x A-pack
__device__ __align__(256) uint32_t g_wpb[(size_t)2048 * KW3];        // W_proj B-pack
__device__ __align__(256) uint32_t g_wob[(size_t)1024 * KW3];        // W_out B-pack
__device__ __align__(256) uint32_t g_na[(size_t)MROWS * KW3];        // nudged A-pack
__device__ __align__(256) uint32_t g_qa[(size_t)32 * 2048 * QW];     // Q A-pack per (b,h)
__device__ __align__(256) uint32_t g_kb[(size_t)32 * 2048 * QW];     // K B-pack per (b,h)
__device__ __align__(256) uint32_t g_vth[(size_t)32 * 64 * 1024];    // V^T hi plane (bf16x2)
__device__ __align__(256) uint32_t g_vtl[(size_t)32 * 64 * 1024];    // V^T lo plane (bf16x2)

// ---------------- helpers ----------------
__device__ __forceinline__ uint32_t smem_u32(const void* p) {
    uint32_t a;
    asm("{ .reg .u64 t; cvta.to.shared.u64 t, %1; cvt.u32.u64 %0, t; }" : "=r"(a) : "l"(p));
    return a;
}
__device__ __forceinline__ void bf3_split(float x, uint32_t& h, uint32_t& l) {
    __nv_bfloat16 bh = __float2bfloat16_rn(x);
    float hf = __bfloat162float(bh);
    __nv_bfloat16 bl = __float2bfloat16_rn(x - hf);
    h = (uint32_t)__bfloat16_as_ushort(bh);
    l = (uint32_t)__bfloat16_as_ushort(bl);
}
__device__ __forceinline__ void packA2(float x0, float x1, uint32_t* u) {
    uint32_t h0, l0, h1, l1;
    bf3_split(x0, h0, l0); bf3_split(x1, h1, l1);
    u[0] = h0 | (l0 << 16); u[1] = h0 | (h1 << 16); u[2] = l1 | (h1 << 16);
}
__device__ __forceinline__ void packB2(float x0, float x1, uint32_t* u) {
    uint32_t h0, l0, h1, l1;
    bf3_split(x0, h0, l0); bf3_split(x1, h1, l1);
    u[0] = h0 | (h0 << 16); u[1] = l0 | (h1 << 16); u[2] = h1 | (l1 << 16);
}
__device__ __forceinline__ void split_pair(float a, float b, uint32_t& hi, uint32_t& lo) {
    __nv_bfloat16 ah = __float2bfloat16_rn(a), bh = __float2bfloat16_rn(b);
    float af = __bfloat162float(ah), bf = __bfloat162float(bh);
    __nv_bfloat16 al = __float2bfloat16_rn(a - af), bl = __float2bfloat16_rn(b - bf);
    hi = (uint32_t)__bfloat16_as_ushort(ah) | ((uint32_t)__bfloat16_as_ushort(bh) << 16);
    lo = (uint32_t)__bfloat16_as_ushort(al) | ((uint32_t)__bfloat16_as_ushort(bl) << 16);
}
__device__ __forceinline__ void mma16816(float* d, const uint32_t* a, const uint32_t* b) {
    asm("mma.sync.aligned.m16n8k16.row.col.f32.bf16.bf16.f32 "
        "{%0,%1,%2,%3}, {%4,%5,%6,%7}, {%8,%9}, {%0,%1,%2,%3};"
        : "+f"(d[0]), "+f"(d[1]), "+f"(d[2]), "+f"(d[3])
        : "r"(a[0]), "r"(a[1]), "r"(a[2]), "r"(a[3]), "r"(b[0]), "r"(b[1]));
}
__device__ __forceinline__ void ldsm_x4(uint32_t* r, uint32_t addr) {
    asm volatile("ldmatrix.sync.aligned.m8n8.x4.shared.b16 {%0,%1,%2,%3}, [%4];"
        : "=r"(r[0]), "=r"(r[1]), "=r"(r[2]), "=r"(r[3]) : "r"(addr));
}
__device__ __forceinline__ void cp16(uint32_t dst, const void* src) {
    asm volatile("cp.async.cg.shared.global [%0], [%1], 16;" :: "r"(dst), "l"(src) : "memory");
}
#define CP_COMMIT() asm volatile("cp.async.commit_group;" ::: "memory")
#define CP_WAIT(n)  asm volatile("cp.async.wait_group %0;" :: "n"(n) : "memory")

// ---------------- one fused one-time pack kernel ----------------
#define NTASK_X  (MROWS * 512)
#define NTASK_WP (2048 * 512)
#define NTASK_WO (1024 * 512)
__global__ void pack_all(const float* __restrict__ x, const float* __restrict__ Wp,
                         const float* __restrict__ Wo,
                         uint32_t* __restrict__ xa, uint32_t* __restrict__ wpb,
                         uint32_t* __restrict__ wob) {
    int idx = blockIdx.x * 256 + threadIdx.x;
    const float* src; uint32_t* dst; int aform;
    if (idx < NTASK_X)                   { src = x;  dst = xa;  aform = 1; }
    else if (idx < NTASK_X + NTASK_WP)   { src = Wp; dst = wpb; aform = 0; idx -= NTASK_X; }
    else if (idx < NTASK_X + NTASK_WP + NTASK_WO)
                                         { src = Wo; dst = wob; aform = 0; idx -= NTASK_X + NTASK_WP; }
    else return;
    int row = idx >> 9, kp = idx & 511;
    float2 v = *(const float2*)(src + (size_t)row * 1024 + 2 * kp);
    uint32_t u[3];
    if (aform) packA2(v.x, v.y, u); else packB2(v.x, v.y, u);
    size_t o = (size_t)row * KW3 + 3 * kp;
    dst[o] = u[0]; dst[o + 1] = u[1]; dst[o + 2] = u[2];
}

// V transpose + hi/lo bf16 planes
__global__ __launch_bounds__(256) void vt_pack(const float* __restrict__ vf,
                                               uint32_t* __restrict__ vth,
                                               uint32_t* __restrict__ vtl) {
    __shared__ float smv[128][65];
    const int tid = threadIdx.x;
    const int wc = blockIdx.x, bh = blockIdx.y;
    const int b = bh >> 4, h = bh & 15;
    const int w0 = wc * 128;
    const float* src = vf + ((size_t)(b * 2048) + w0) * 1024 + h * 64;
#pragma unroll
    for (int i = 0; i < 8; i++) {
        int idx = i * 256 + tid, w = idx >> 4, c4 = (idx & 15) * 4;
        float4 v = *(const float4*)(src + (size_t)w * 1024 + c4);
        smv[w][c4] = v.x; smv[w][c4 + 1] = v.y; smv[w][c4 + 2] = v.z; smv[w][c4 + 3] = v.w;
    }
    __syncthreads();
#pragma unroll
    for (int i = 0; i < 16; i++) {
        int task = i * 256 + tid;
        int n = task >> 6, wp = task & 63;
        uint32_t hi, lo;
        split_pair(smv[2 * wp][n], smv[2 * wp + 1][n], hi, lo);
        size_t o = ((size_t)bh * 64 + n) * 1024 + (w0 >> 1) + wp;
        vth[o] = hi; vtl[o] = lo;
    }
}

// ---------------- GEMM: chunk-32, 2-stage, one barrier per chunk (R8) ---------
#define STRG 52
#define CW   48
#define NCHG 32
#define ATW  (128 * STRG)
#define BUFW (2 * ATW)
#define GSMEMB (2 * BUFW * 4)      /* 106496 B */

__global__ __launch_bounds__(256, 2) void gemm_pk(
    const uint32_t* __restrict__ Ap, const uint32_t* __restrict__ Bp,
    float* __restrict__ C, int N, int mode,
    uint32_t* __restrict__ qa, uint32_t* __restrict__ kb, float* __restrict__ vf)
{
    extern __shared__ uint32_t sw[];
    const uint32_t sbase = smem_u32(sw);
    const int tid = threadIdx.x, lane = tid & 31, wid = tid >> 5;
    const int g = lane >> 2, t = lane & 3, rowInM = lane & 7, j = lane >> 3;
    const int m0 = blockIdx.y * 128, n0 = blockIdx.x * 128;
    const int wm = wid >> 2, wn = wid & 3;

    const uint32_t* Arow = Ap + (size_t)m0 * KW3;
    const uint32_t* Brow = Bp + (size_t)n0 * KW3;

#define GISSUE(c_, buf_) do { \
    uint32_t dA_ = sbase + (buf_) * BUFW * 4; \
    uint32_t dB_ = dA_ + ATW * 4; \
    _Pragma("unroll") \
    for (int i_ = 0; i_ < 6; i_++) { \
        int idx_ = i_ * 256 + tid, row_ = idx_ / 12, q_ = idx_ % 12; \
        cp16(dA_ + (row_ * STRG + q_ * 4) * 4, Arow + (size_t)row_ * KW3 + (c_) * CW + q_ * 4); \
    } \
    _Pragma("unroll") \
    for (int i_ = 0; i_ < 6; i_++) { \
        int idx_ = i_ * 256 + tid, row_ = idx_ / 12, q_ = idx_ % 12; \
        cp16(dB_ + (row_ * STRG + q_ * 4) * 4, Brow + (size_t)row_ * KW3 + (c_) * CW + q_ * 4); \
    } \
    CP_COMMIT(); } while (0)

    GISSUE(0, 0);

    float acc[4][4][4] = {};

    for (int c = 0; c < NCHG; c++) {
        CP_WAIT(0);
        __syncthreads();
        if (c + 1 < NCHG) GISSUE(c + 1, (c + 1) & 1);

        const uint32_t abase = sbase + (c & 1) * BUFW * 4;
        const uint32_t bbase = abase + ATW * 4;
#pragma unroll
        for (int ks = 0; ks < 6; ks++) {
            uint32_t af[4][4], bf2[2][4];
#pragma unroll
            for (int mf = 0; mf < 4; mf++)
                ldsm_x4(af[mf], abase + ((wm * 64 + mf * 16 + rowInM + 8 * (j & 1)) * STRG
                                          + ks * 8 + 4 * (j >> 1)) * 4);
#pragma unroll
            for (int p = 0; p < 2; p++)
                ldsm_x4(bf2[p], bbase + ((wn * 32 + p * 16 + (j >> 1) * 8 + rowInM) * STRG
                                          + ks * 8 + 4 * (j & 1)) * 4);
#pragma unroll
            for (int mf = 0; mf < 4; mf++)
#pragma unroll
                for (int nf = 0; nf < 4; nf++)
                    mma16816(acc[mf][nf], af[mf], &bf2[nf >> 1][(nf & 1) * 2]);
        }
    }

    if (mode == 0) {
#pragma unroll
        for (int mf = 0; mf < 4; mf++)
#pragma unroll
            for (int nf = 0; nf < 4; nf++) {
                int r = m0 + wm * 64 + mf * 16 + g;
                int cc = n0 + wn * 32 + nf * 8 + 2 * t;
                *(float2*)(C + (size_t)r * N + cc) =
                    make_float2(acc[mf][nf][0], acc[mf][nf][1]);
                *(float2*)(C + (size_t)(r + 8) * N + cc) =
                    make_float2(acc[mf][nf][2], acc[mf][nf][3]);
            }
    } else {
#pragma unroll
        for (int mf = 0; mf < 4; mf++)
#pragma unroll
            for (int nf = 0; nf < 4; nf++) {
                int r1 = m0 + wm * 64 + mf * 16 + g;
                int cc = n0 + wn * 32 + nf * 8 + 2 * t;
                if (cc < 1024) {
                    int hh = cc >> 6, kc = cc & 63;
#pragma unroll
                    for (int half = 0; half < 2; half++) {
                        int r = r1 + 8 * half;
                        int bb = r >> 11, w = r & 2047;
                        size_t base = ((size_t)(bb * 16 + hh) * 2048 + w) * QW + 3 * (kc >> 1);
                        uint32_t u[3];
                        packA2(acc[mf][nf][2 * half], acc[mf][nf][2 * half + 1], u);
                        qa[base] = u[0]; qa[base + 1] = u[1]; qa[base + 2] = u[2];
                        packB2(acc[mf][nf][2 * half], acc[mf][nf][2 * half + 1], u);
                        kb[base] = u[0]; kb[base + 1] = u[1]; kb[base + 2] = u[2];
                    }
                } else {
                    int cv = cc - 1024;
                    *(float2*)(vf + (size_t)r1 * 1024 + cv) =
                        make_float2(acc[mf][nf][0], acc[mf][nf][1]);
                    *(float2*)(vf + (size_t)(r1 + 8) * 1024 + cv) =
                        make_float2(acc[mf][nf][2], acc[mf][nf][3]);
                }
            }
    }
#undef GISSUE
}

// ---------------- fused causal attention: 128 threads, 64 q rows, 2 CTAs/SM ---
// 4 warps: wq in {0,1} (32 q rows each), wlo in {0,1} (32-s slice each).
// SMEM words: Q[64x100] | K x2 [64x100] | V planes
#define STRA    100
#define QTW     6400                 /* 64 * 100 */
#define KBW     6400
#define VPLANEB 9216                 /* 64 rows * 144 B */
#define VBUFB   (2 * VPLANEB)
#define VBASEB  ((QTW + 2 * KBW) * 4)  /* 76800 */
#define ASMEMB  (VBASEB + 2 * VBUFB)   /* 113664 B */

__global__ __launch_bounds__(128, 2) void attn_pk(
    const uint32_t* __restrict__ qa, const uint32_t* __restrict__ kbuf,
    const uint32_t* __restrict__ vth, const uint32_t* __restrict__ vtl,
    uint32_t* __restrict__ na)
{
    extern __shared__ uint32_t sw[];
    const uint32_t sbase = smem_u32(sw);
    const int tid = threadIdx.x, lane = tid & 31, wid = tid >> 5;
    const int g = lane >> 2, t = lane & 3, rowInM = lane & 7, j = lane >> 3;
    const int qt = 31 - blockIdx.x;           // largest-work tiles first
    const int q0 = qt * 64;
    const int bh = blockIdx.y, b = bh >> 4, h = bh & 15;
    const int wq = wid >> 1, wlo = wid & 1;

    const uint32_t* qrow = qa + ((size_t)bh * 2048 + q0) * QW;
    const uint32_t* krow = kbuf + (size_t)bh * 2048 * QW;
    const uint32_t* vhp = vth + (size_t)bh * 64 * 1024;
    const uint32_t* vlp = vtl + (size_t)bh * 64 * 1024;

#define KVISSUE(sb_, buf_) do { \
    uint32_t kdst_ = sbase + (QTW + (buf_) * KBW) * 4; \
    _Pragma("unroll") \
    for (int i_ = 0; i_ < 12; i_++) { \
        int idx_ = i_ * 128 + tid, row_ = idx_ / 24, q_ = idx_ % 24; \
        cp16(kdst_ + (row_ * STRA + q_ * 4) * 4, \
             krow + (size_t)((sb_) * 64 + row_) * QW + q_ * 4); \
    } \
    uint32_t vdst_ = sbase + VBASEB + (buf_) * VBUFB; \
    _Pragma("unroll") \
    for (int i_ = 0; i_ < 4; i_++) { \
        int idx_ = i_ * 128 + tid, row_ = idx_ >> 3, q_ = idx_ & 7; \
        cp16(vdst_ + row_ * 144 + q_ * 16, \
             vhp + (size_t)row_ * 1024 + (sb_) * 32 + q_ * 4); \
        cp16(vdst_ + VPLANEB + row_ * 144 + q_ * 16, \
             vlp + (size_t)row_ * 1024 + (sb_) * 32 + q_ * 4); \
    } \
    CP_COMMIT(); } while (0)

    // prologue: Q tile (64 rows) + KV block 0
#pragma unroll
    for (int i = 0; i < 12; i++) {
        int idx = i * 128 + tid, row = idx / 24, q = idx % 24;
        cp16(sbase + (row * STRA + q * 4) * 4, qrow + (size_t)row * QW + q * 4);
    }
    KVISSUE(0, 0);

    float oacc[2][8][4] = {};
    const int nS = qt + 1;                    // s-blocks 0..qt

    for (int sb = 0; sb < nS; sb++) {
        CP_WAIT(0);
        __syncthreads();
        if (sb + 1 < nS) KVISSUE(sb + 1, (sb + 1) & 1);

        const uint32_t kbs = sbase + (QTW + (sb & 1) * KBW) * 4;
        const uint32_t vbs = sbase + VBASEB + (sb & 1) * VBUFB;

        // ---- QK: warp tile 32q x 32s ----
        float sacc[2][4][4] = {};
#pragma unroll
        for (int ks = 0; ks < 12; ks++) {
            uint32_t af[2][4], bf2[2][4];
#pragma unroll
            for (int mf = 0; mf < 2; mf++)
                ldsm_x4(af[mf], sbase + ((wq * 32 + mf * 16 + rowInM + 8 * (j & 1)) * STRA
                                          + ks * 8 + 4 * (j >> 1)) * 4);
#pragma unroll
            for (int p = 0; p < 2; p++)
                ldsm_x4(bf2[p], kbs + ((wlo * 32 + p * 16 + (j >> 1) * 8 + rowInM) * STRA
                                        + ks * 8 + 4 * (j & 1)) * 4);
#pragma unroll
            for (int mf = 0; mf < 2; mf++)
#pragma unroll
                for (int nf = 0; nf < 4; nf++)
                    mma16816(sacc[mf][nf], af[mf], &bf2[nf >> 1][(nf & 1) * 2]);
        }

        // ---- scale (+ mask only on diagonal-crossing warp blocks) ----
        const int s0w = sb * 64 + wlo * 32;
        const int q0w = q0 + wq * 32;
        if (s0w + 31 <= q0w) {
#pragma unroll
            for (int mf = 0; mf < 2; mf++)
#pragma unroll
                for (int nf = 0; nf < 4; nf++)
#pragma unroll
                    for (int e = 0; e < 4; e++)
                        sacc[mf][nf][e] *= 0.125f;
        } else {
#pragma unroll
            for (int mf = 0; mf < 2; mf++)
#pragma unroll
                for (int nf = 0; nf < 4; nf++)
#pragma unroll
                    for (int e = 0; e < 4; e++) {
                        int sg = s0w + nf * 8 + 2 * t + (e & 1);
                        int qg = q0w + mf * 16 + g + 8 * (e >> 1);
                        sacc[mf][nf][e] = (sg <= qg) ? sacc[mf][nf][e] * 0.125f : 0.f;
                    }
        }

        // ---- SV: A frags from sacc (hi/lo), B from V planes ----
#pragma unroll
        for (int ki = 0; ki < 2; ki++) {
            uint32_t ash[2][4], asl[2][4];
#pragma unroll
            for (int mf = 0; mf < 2; mf++) {
                split_pair(sacc[mf][2 * ki][0],     sacc[mf][2 * ki][1],     ash[mf][0], asl[mf][0]);
                split_pair(sacc[mf][2 * ki][2],     sacc[mf][2 * ki][3],     ash[mf][1], asl[mf][1]);
                split_pair(sacc[mf][2 * ki + 1][0], sacc[mf][2 * ki + 1][1], ash[mf][2], asl[mf][2]);
                split_pair(sacc[mf][2 * ki + 1][2], sacc[mf][2 * ki + 1][3], ash[mf][3], asl[mf][3]);
            }
            uint32_t bh_[4][4], bl_[4][4];
#pragma unroll
            for (int p = 0; p < 4; p++) {
                uint32_t col = wlo * 64 + ki * 32 + (j & 1) * 16;
                uint32_t row = (p * 16 + (j >> 1) * 8 + rowInM) * 144;
                ldsm_x4(bh_[p], vbs + row + col);
                ldsm_x4(bl_[p], vbs + VPLANEB + row + col);
            }
#pragma unroll
            for (int mf = 0; mf < 2; mf++)
#pragma unroll
                for (int nf = 0; nf < 8; nf++) {
                    const uint32_t* bhf = &bh_[nf >> 1][(nf & 1) * 2];
                    const uint32_t* blf = &bl_[nf >> 1][(nf & 1) * 2];
                    mma16816(oacc[mf][nf], ash[mf], bhf);
                    mma16816(oacc[mf][nf], asl[mf], bhf);
                    mma16816(oacc[mf][nf], ash[mf], blf);
                }
        }
    }

    // ---- cross-wlo reduction (scratch over Q area, stride 66) ----
    __syncthreads();
    if (wlo == 1) {
#pragma unroll
        for (int mf = 0; mf < 2; mf++)
#pragma unroll
            for (int nf = 0; nf < 8; nf++)
#pragma unroll
                for (int e = 0; e < 4; e++) {
                    int qloc = mf * 16 + g + 8 * (e >> 1);
                    int n = nf * 8 + 2 * t + (e & 1);
                    sw[wq * 2112 + qloc * 66 + n] = __float_as_uint(oacc[mf][nf][e]);
                }
    }
    __syncthreads();
    if (wlo == 0) {
#pragma unroll
        for (int mf = 0; mf < 2; mf++)
#pragma unroll
            for (int nf = 0; nf < 8; nf++)
#pragma unroll
                for (int half = 0; half < 2; half++) {
                    int qloc = mf * 16 + g + 8 * half;
                    int n = nf * 8 + 2 * t;
                    float sA = oacc[mf][nf][2 * half] +
                               __uint_as_float(sw[wq * 2112 + qloc * 66 + n]);
                    float sB = oacc[mf][nf][2 * half + 1] +
                               __uint_as_float(sw[wq * 2112 + qloc * 66 + n + 1]);
                    uint32_t u[3]; packA2(sA, sB, u);
                    int row = q0 + wq * 32 + qloc;
                    int cc = h * 64 + n;
                    size_t o = (size_t)(b * 2048 + row) * KW3 + 3 * (cc >> 1);
                    na[o] = u[0]; na[o + 1] = u[1]; na[o + 2] = u[2];
                }
    }
#undef KVISSUE
}

// ---------------- kernel_launch ----------------
extern "C" void kernel_launch(void* const* d_in, const int* in_sizes, int n_in,
                              void* d_out, int out_size)
{
    const float* x  = (const float*)d_in[0];
    const float* Wp = (const float*)d_in[1];
    const float* Wo = (const float*)d_in[2];
    float* out = (float*)d_out;

    float* vf;
    uint32_t *xa, *wpb, *wob, *na, *qa, *kb, *vth, *vtl;
    cudaGetSymbolAddress((void**)&vf,  g_v);
    cudaGetSymbolAddress((void**)&xa,  g_xa);
    cudaGetSymbolAddress((void**)&wpb, g_wpb);
    cudaGetSymbolAddress((void**)&wob, g_wob);
    cudaGetSymbolAddress((void**)&na,  g_na);
    cudaGetSymbolAddress((void**)&qa,  g_qa);
    cudaGetSymbolAddress((void**)&kb,  g_kb);
    cudaGetSymbolAddress((void**)&vth, g_vth);
    cudaGetSymbolAddress((void**)&vtl, g_vtl);

    cudaFuncSetAttribute(gemm_pk, cudaFuncAttributeMaxDynamicSharedMemorySize, GSMEMB);
    cudaFuncSetAttribute(attn_pk, cudaFuncAttributeMaxDynamicSharedMemorySize, ASMEMB);

    {
        int total = NTASK_X + NTASK_WP + NTASK_WO;
        pack_all<<<(total + 255) / 256, 256>>>(x, Wp, Wo, xa, wpb, wob);
    }

    // 1) proj GEMM; epilogue emits Q/K packs + V fp32 staging
    gemm_pk<<<dim3(2048 / 128, MROWS / 128), 256, GSMEMB>>>(
        xa, wpb, nullptr, 2048, 1, qa, kb, vf);

    // V transpose -> hi/lo bf16 planes
    vt_pack<<<dim3(WTOT / 128, 32), 256>>>(vf, vth, vtl);

    // 2) fused causal attention (64-q CTAs, 2/SM); epilogue emits nudged A-pack
    attn_pk<<<dim3(32, 32), 128, ASMEMB>>>(qa, kb, vth, vtl, na);

    // 3) output GEMM -> fp32 out
    gemm_pk<<<dim3(1024 / 128, MROWS / 128), 256, GSMEMB>>>(
        na, wob, out, 1024, 0, nullptr, nullptr, nullptr);
}

// round 11
// speedup vs baseline: 2.7469x; 1.1332x over previous
#include <cuda_runtime.h>
#include <cuda_bf16.h>
#include <cstdint>
#include <cstddef>

#define WTOT  2048
#define CDIM  1024
#define MROWS 4096
#define KWP   1024      /* plane words per K=1024 row: hi 512 | lo 512 */

// ---------------- scratch (no allocation allowed) ----------------
__device__ __align__(256) float    g_v[(size_t)MROWS * CDIM];        // V fp32 staging
__device__ __align__(256) uint32_t g_xa[(size_t)MROWS * KWP];        // x planes
__device__ __align__(256) uint32_t g_wpb[(size_t)2048 * KWP];        // W_proj planes
__device__ __align__(256) uint32_t g_wob[(size_t)1024 * KWP];        // W_out planes
__device__ __align__(256) uint32_t g_na[(size_t)MROWS * KWP];        // nudged planes
__device__ __align__(256) uint32_t g_qk[(size_t)32 * 2048 * 64];     // Q/K unified planes
__device__ __align__(256) uint32_t g_vth[(size_t)32 * 64 * 1024];    // V^T hi plane
__device__ __align__(256) uint32_t g_vtl[(size_t)32 * 64 * 1024];    // V^T lo plane

// ---------------- helpers ----------------
__device__ __forceinline__ uint32_t smem_u32(const void* p) {
    uint32_t a;
    asm("{ .reg .u64 t; cvta.to.shared.u64 t, %1; cvt.u32.u64 %0, t; }" : "=r"(a) : "l"(p));
    return a;
}
// split two floats into (hi pair, lo pair) bf16x2 words
__device__ __forceinline__ void split_pair(float a, float b, uint32_t& hi, uint32_t& lo) {
    __nv_bfloat16 ah = __float2bfloat16_rn(a), bh = __float2bfloat16_rn(b);
    float af = __bfloat162float(ah), bf = __bfloat162float(bh);
    __nv_bfloat16 al = __float2bfloat16_rn(a - af), bl = __float2bfloat16_rn(b - bf);
    hi = (uint32_t)__bfloat16_as_ushort(ah) | ((uint32_t)__bfloat16_as_ushort(bh) << 16);
    lo = (uint32_t)__bfloat16_as_ushort(al) | ((uint32_t)__bfloat16_as_ushort(bl) << 16);
}
__device__ __forceinline__ void mma16816(float* d, const uint32_t* a, const uint32_t* b) {
    asm("mma.sync.aligned.m16n8k16.row.col.f32.bf16.bf16.f32 "
        "{%0,%1,%2,%3}, {%4,%5,%6,%7}, {%8,%9}, {%0,%1,%2,%3};"
        : "+f"(d[0]), "+f"(d[1]), "+f"(d[2]), "+f"(d[3])
        : "r"(a[0]), "r"(a[1]), "r"(a[2]), "r"(a[3]), "r"(b[0]), "r"(b[1]));
}
__device__ __forceinline__ void ldsm_x4(uint32_t* r, uint32_t addr) {
    asm volatile("ldmatrix.sync.aligned.m8n8.x4.shared.b16 {%0,%1,%2,%3}, [%4];"
        : "=r"(r[0]), "=r"(r[1]), "=r"(r[2]), "=r"(r[3]) : "r"(addr));
}
__device__ __forceinline__ void cp16(uint32_t dst, const void* src) {
    asm volatile("cp.async.cg.shared.global [%0], [%1], 16;" :: "r"(dst), "l"(src) : "memory");
}
#define CP_COMMIT() asm volatile("cp.async.commit_group;" ::: "memory")
#define CP_WAIT(n)  asm volatile("cp.async.wait_group %0;" :: "n"(n) : "memory")

// ---------------- one fused one-time plane-split kernel ----------------
// every tensor -> [row][hi 512 words | lo 512 words]
#define NTASK_X  (MROWS * 512)
#define NTASK_WP (2048 * 512)
#define NTASK_WO (1024 * 512)
__global__ void pack_all(const float* __restrict__ x, const float* __restrict__ Wp,
                         const float* __restrict__ Wo,
                         uint32_t* __restrict__ xa, uint32_t* __restrict__ wpb,
                         uint32_t* __restrict__ wob) {
    int idx = blockIdx.x * 256 + threadIdx.x;
    const float* src; uint32_t* dst;
    if (idx < NTASK_X)                 { src = x;  dst = xa; }
    else if (idx < NTASK_X + NTASK_WP) { src = Wp; dst = wpb; idx -= NTASK_X; }
    else if (idx < NTASK_X + NTASK_WP + NTASK_WO)
                                       { src = Wo; dst = wob; idx -= NTASK_X + NTASK_WP; }
    else return;
    int row = idx >> 9, kp = idx & 511;
    float2 v = *(const float2*)(src + (size_t)row * 1024 + 2 * kp);
    uint32_t hi, lo;
    split_pair(v.x, v.y, hi, lo);
    dst[(size_t)row * KWP + kp] = hi;
    dst[(size_t)row * KWP + 512 + kp] = lo;
}

// V transpose + hi/lo bf16 planes
__global__ __launch_bounds__(256) void vt_pack(const float* __restrict__ vf,
                                               uint32_t* __restrict__ vth,
                                               uint32_t* __restrict__ vtl) {
    __shared__ float smv[128][65];
    const int tid = threadIdx.x;
    const int wc = blockIdx.x, bh = blockIdx.y;
    const int b = bh >> 4, h = bh & 15;
    const int w0 = wc * 128;
    const float* src = vf + ((size_t)(b * 2048) + w0) * 1024 + h * 64;
#pragma unroll
    for (int i = 0; i < 8; i++) {
        int idx = i * 256 + tid, w = idx >> 4, c4 = (idx & 15) * 4;
        float4 v = *(const float4*)(src + (size_t)w * 1024 + c4);
        smv[w][c4] = v.x; smv[w][c4 + 1] = v.y; smv[w][c4 + 2] = v.z; smv[w][c4 + 3] = v.w;
    }
    __syncthreads();
#pragma unroll
    for (int i = 0; i < 16; i++) {
        int task = i * 256 + tid;
        int n = task >> 6, wp = task & 63;
        uint32_t hi, lo;
        split_pair(smv[2 * wp][n], smv[2 * wp + 1][n], hi, lo);
        size_t o = ((size_t)bh * 64 + n) * 1024 + (w0 >> 1) + wp;
        vth[o] = hi; vtl[o] = lo;
    }
}

// ---------------- GEMM on planes: chunk-32 fp32, 2-stage, 1 barrier/chunk -----
// smem row per chunk: [hi 16 words | lo 16 words] + 4 pad, stride 36.
#define STRG 36
#define NCHG 32
#define ATW  (128 * STRG)           /* 4608 words per operand per stage */
#define BUFW (2 * ATW)              /* 9216 */
#define GSMEMB (2 * BUFW * 4)       /* 73728 B */

__global__ __launch_bounds__(256, 2) void gemm_pl(
    const uint32_t* __restrict__ Ap, const uint32_t* __restrict__ Bp,
    float* __restrict__ C, int N, int mode,
    uint32_t* __restrict__ qk, float* __restrict__ vf)
{
    extern __shared__ uint32_t sw[];
    const uint32_t sbase = smem_u32(sw);
    const int tid = threadIdx.x, lane = tid & 31, wid = tid >> 5;
    const int g = lane >> 2, t = lane & 3, rowInM = lane & 7, j = lane >> 3;
    const int m0 = blockIdx.y * 128, n0 = blockIdx.x * 128;
    const int wm = wid >> 2, wn = wid & 3;

    const uint32_t* Arow = Ap + (size_t)m0 * KWP;
    const uint32_t* Brow = Bp + (size_t)n0 * KWP;

    // per chunk c: hi words c*16..+15, lo words 512+c*16..+15
#define GISSUE(c_, buf_) do { \
    uint32_t dA_ = sbase + (buf_) * BUFW * 4; \
    uint32_t dB_ = dA_ + ATW * 4; \
    _Pragma("unroll") \
    for (int i_ = 0; i_ < 4; i_++) { \
        int idx_ = i_ * 256 + tid, row_ = idx_ >> 3, q_ = idx_ & 7; \
        int so_ = (q_ < 4) ? ((c_) * 16 + q_ * 4) : (512 + (c_) * 16 + (q_ - 4) * 4); \
        cp16(dA_ + (row_ * STRG + q_ * 4) * 4, Arow + (size_t)row_ * KWP + so_); \
    } \
    _Pragma("unroll") \
    for (int i_ = 0; i_ < 4; i_++) { \
        int idx_ = i_ * 256 + tid, row_ = idx_ >> 3, q_ = idx_ & 7; \
        int so_ = (q_ < 4) ? ((c_) * 16 + q_ * 4) : (512 + (c_) * 16 + (q_ - 4) * 4); \
        cp16(dB_ + (row_ * STRG + q_ * 4) * 4, Brow + (size_t)row_ * KWP + so_); \
    } \
    CP_COMMIT(); } while (0)

    GISSUE(0, 0);

    float acc[4][4][4] = {};

    for (int c = 0; c < NCHG; c++) {
        CP_WAIT(0);
        __syncthreads();
        if (c + 1 < NCHG) GISSUE(c + 1, (c + 1) & 1);

        const uint32_t abase = sbase + (c & 1) * BUFW * 4;
        const uint32_t bbase = abase + ATW * 4;
#pragma unroll
        for (int s4 = 0; s4 < 2; s4++) {      // k16 steps in chunk
            uint32_t ah[4][4], bh2[2][4], bl2[2][4];
#pragma unroll
            for (int mf = 0; mf < 4; mf++)
                ldsm_x4(ah[mf], abase + ((wm * 64 + mf * 16 + rowInM + 8 * (j & 1)) * STRG
                                          + s4 * 8 + 4 * (j >> 1)) * 4);
#pragma unroll
            for (int p = 0; p < 2; p++) {
                uint32_t brow = (wn * 32 + p * 16 + (j >> 1) * 8 + rowInM) * STRG
                                + s4 * 8 + 4 * (j & 1);
                ldsm_x4(bh2[p], bbase + brow * 4);
                ldsm_x4(bl2[p], bbase + (brow + 16) * 4);
            }
#pragma unroll
            for (int mf = 0; mf < 4; mf++)
#pragma unroll
                for (int nf = 0; nf < 4; nf++) {
                    const uint32_t* bhf = &bh2[nf >> 1][(nf & 1) * 2];
                    const uint32_t* blf = &bl2[nf >> 1][(nf & 1) * 2];
                    mma16816(acc[mf][nf], ah[mf], bhf);
                    mma16816(acc[mf][nf], ah[mf], blf);
                }
            uint32_t al[4][4];
#pragma unroll
            for (int mf = 0; mf < 4; mf++)
                ldsm_x4(al[mf], abase + ((wm * 64 + mf * 16 + rowInM + 8 * (j & 1)) * STRG
                                          + 16 + s4 * 8 + 4 * (j >> 1)) * 4);
#pragma unroll
            for (int mf = 0; mf < 4; mf++)
#pragma unroll
                for (int nf = 0; nf < 4; nf++)
                    mma16816(acc[mf][nf], al[mf], &bh2[nf >> 1][(nf & 1) * 2]);
        }
    }

    // ---- epilogue ----
    if (mode == 0) {
#pragma unroll
        for (int mf = 0; mf < 4; mf++)
#pragma unroll
            for (int nf = 0; nf < 4; nf++) {
                int r = m0 + wm * 64 + mf * 16 + g;
                int cc = n0 + wn * 32 + nf * 8 + 2 * t;
                *(float2*)(C + (size_t)r * N + cc) =
                    make_float2(acc[mf][nf][0], acc[mf][nf][1]);
                *(float2*)(C + (size_t)(r + 8) * N + cc) =
                    make_float2(acc[mf][nf][2], acc[mf][nf][3]);
            }
    } else {
        // GEMM1: cols [0,1024) -> unified Q/K planes; cols [1024,2048) -> V fp32
#pragma unroll
        for (int mf = 0; mf < 4; mf++)
#pragma unroll
            for (int nf = 0; nf < 4; nf++) {
                int r1 = m0 + wm * 64 + mf * 16 + g;
                int cc = n0 + wn * 32 + nf * 8 + 2 * t;
                if (cc < 1024) {
                    int hh = cc >> 6, kc = cc & 63;
#pragma unroll
                    for (int half = 0; half < 2; half++) {
                        int r = r1 + 8 * half;
                        int bb = r >> 11, w = r & 2047;
                        uint32_t* rowp = qk + ((size_t)(bb * 16 + hh) * 2048 + w) * 64;
                        uint32_t hi, lo;
                        split_pair(acc[mf][nf][2 * half], acc[mf][nf][2 * half + 1], hi, lo);
                        rowp[(kc >> 1)] = hi;
                        rowp[32 + (kc >> 1)] = lo;
                    }
                } else {
                    int cv = cc - 1024;
                    *(float2*)(vf + (size_t)r1 * 1024 + cv) =
                        make_float2(acc[mf][nf][0], acc[mf][nf][1]);
                    *(float2*)(vf + (size_t)(r1 + 8) * 1024 + cv) =
                        make_float2(acc[mf][nf][2], acc[mf][nf][3]);
                }
            }
    }
#undef GISSUE
}

// ---------------- fused causal attention on unified Q/K planes ----------------
// CTA = 64 q rows, 128 threads, 2 CTAs/SM. Row = 64 words [hi32|lo32], stride 68.
#define STRA    68
#define QTW     (64 * STRA)            /* 4352 */
#define KBW     (64 * STRA)
#define VPLANEB 9216                   /* 64 rows * 144 B */
#define VBUFB   (2 * VPLANEB)
#define VBASEB  ((QTW + 2 * KBW) * 4)  /* 52224 */
#define ASMEMB  (VBASEB + 2 * VBUFB)   /* 89088 B */

__global__ __launch_bounds__(128, 2) void attn_pl(
    const uint32_t* __restrict__ qk,
    const uint32_t* __restrict__ vth, const uint32_t* __restrict__ vtl,
    uint32_t* __restrict__ na)
{
    extern __shared__ uint32_t sw[];
    const uint32_t sbase = smem_u32(sw);
    const int tid = threadIdx.x, lane = tid & 31, wid = tid >> 5;
    const int g = lane >> 2, t = lane & 3, rowInM = lane & 7, j = lane >> 3;
    const int qt = 31 - blockIdx.x;           // largest-work tiles first
    const int q0 = qt * 64;
    const int bh = blockIdx.y, b = bh >> 4, h = bh & 15;
    const int wq = wid >> 1, wlo = wid & 1;

    const uint32_t* qkrow = qk + (size_t)bh * 2048 * 64;
    const uint32_t* qrow  = qkrow + (size_t)q0 * 64;
    const uint32_t* vhp = vth + (size_t)bh * 64 * 1024;
    const uint32_t* vlp = vtl + (size_t)bh * 64 * 1024;

#define KVISSUE(sb_, buf_) do { \
    uint32_t kdst_ = sbase + (QTW + (buf_) * KBW) * 4; \
    _Pragma("unroll") \
    for (int i_ = 0; i_ < 8; i_++) { \
        int idx_ = i_ * 128 + tid, row_ = idx_ >> 4, q_ = idx_ & 15; \
        cp16(kdst_ + (row_ * STRA + q_ * 4) * 4, \
             qkrow + (size_t)((sb_) * 64 + row_) * 64 + q_ * 4); \
    } \
    uint32_t vdst_ = sbase + VBASEB + (buf_) * VBUFB; \
    _Pragma("unroll") \
    for (int i_ = 0; i_ < 4; i_++) { \
        int idx_ = i_ * 128 + tid, row_ = idx_ >> 3, q_ = idx_ & 7; \
        cp16(vdst_ + row_ * 144 + q_ * 16, \
             vhp + (size_t)row_ * 1024 + (sb_) * 32 + q_ * 4); \
        cp16(vdst_ + VPLANEB + row_ * 144 + q_ * 16, \
             vlp + (size_t)row_ * 1024 + (sb_) * 32 + q_ * 4); \
    } \
    CP_COMMIT(); } while (0)

    // prologue: Q tile (64 rows x 64 words) + KV block 0
#pragma unroll
    for (int i = 0; i < 8; i++) {
        int idx = i * 128 + tid, row = idx >> 4, q = idx & 15;
        cp16(sbase + (row * STRA + q * 4) * 4, qrow + (size_t)row * 64 + q * 4);
    }
    KVISSUE(0, 0);

    float oacc[2][8][4] = {};
    const int nS = qt + 1;

    for (int sb = 0; sb < nS; sb++) {
        CP_WAIT(0);
        __syncthreads();
        if (sb + 1 < nS) KVISSUE(sb + 1, (sb + 1) & 1);

        const uint32_t kbs = sbase + (QTW + (sb & 1) * KBW) * 4;
        const uint32_t vbs = sbase + VBASEB + (sb & 1) * VBUFB;

        // ---- QK: warp tile 32q x 32s, 4 k16 steps, 3-term planes ----
        float sacc[2][4][4] = {};
#pragma unroll
        for (int s4 = 0; s4 < 4; s4++) {
            uint32_t qh[2][4], ql[2][4], kh2[2][4], kl2[2][4];
#pragma unroll
            for (int mf = 0; mf < 2; mf++) {
                uint32_t arow = (wq * 32 + mf * 16 + rowInM + 8 * (j & 1)) * STRA
                                + s4 * 8 + 4 * (j >> 1);
                ldsm_x4(qh[mf], sbase + arow * 4);
                ldsm_x4(ql[mf], sbase + (arow + 32) * 4);
            }
#pragma unroll
            for (int p = 0; p < 2; p++) {
                uint32_t brow = (wlo * 32 + p * 16 + (j >> 1) * 8 + rowInM) * STRA
                                + s4 * 8 + 4 * (j & 1);
                ldsm_x4(kh2[p], kbs + brow * 4);
                ldsm_x4(kl2[p], kbs + (brow + 32) * 4);
            }
#pragma unroll
            for (int mf = 0; mf < 2; mf++)
#pragma unroll
                for (int nf = 0; nf < 4; nf++) {
                    const uint32_t* khf = &kh2[nf >> 1][(nf & 1) * 2];
                    const uint32_t* klf = &kl2[nf >> 1][(nf & 1) * 2];
                    mma16816(sacc[mf][nf], qh[mf], khf);
                    mma16816(sacc[mf][nf], ql[mf], khf);
                    mma16816(sacc[mf][nf], qh[mf], klf);
                }
        }

        // ---- scale (+ mask only on diagonal-crossing warp blocks) ----
        const int s0w = sb * 64 + wlo * 32;
        const int q0w = q0 + wq * 32;
        if (s0w + 31 <= q0w) {
#pragma unroll
            for (int mf = 0; mf < 2; mf++)
#pragma unroll
                for (int nf = 0; nf < 4; nf++)
#pragma unroll
                    for (int e = 0; e < 4; e++)
                        sacc[mf][nf][e] *= 0.125f;
        } else {
#pragma unroll
            for (int mf = 0; mf < 2; mf++)
#pragma unroll
                for (int nf = 0; nf < 4; nf++)
#pragma unroll
                    for (int e = 0; e < 4; e++) {
                        int sg = s0w + nf * 8 + 2 * t + (e & 1);
                        int qg = q0w + mf * 16 + g + 8 * (e >> 1);
                        sacc[mf][nf][e] = (sg <= qg) ? sacc[mf][nf][e] * 0.125f : 0.f;
                    }
        }

        // ---- SV: A frags from sacc (hi/lo), B from V planes ----
#pragma unroll
        for (int ki = 0; ki < 2; ki++) {
            uint32_t ash[2][4], asl[2][4];
#pragma unroll
            for (int mf = 0; mf < 2; mf++) {
                split_pair(sacc[mf][2 * ki][0],     sacc[mf][2 * ki][1],     ash[mf][0], asl[mf][0]);
                split_pair(sacc[mf][2 * ki][2],     sacc[mf][2 * ki][3],     ash[mf][1], asl[mf][1]);
                split_pair(sacc[mf][2 * ki + 1][0], sacc[mf][2 * ki + 1][1], ash[mf][2], asl[mf][2]);
                split_pair(sacc[mf][2 * ki + 1][2], sacc[mf][2 * ki + 1][3], ash[mf][3], asl[mf][3]);
            }
            uint32_t bh_[4][4], bl_[4][4];
#pragma unroll
            for (int p = 0; p < 4; p++) {
                uint32_t col = wlo * 64 + ki * 32 + (j & 1) * 16;
                uint32_t row = (p * 16 + (j >> 1) * 8 + rowInM) * 144;
                ldsm_x4(bh_[p], vbs + row + col);
                ldsm_x4(bl_[p], vbs + VPLANEB + row + col);
            }
#pragma unroll
            for (int mf = 0; mf < 2; mf++)
#pragma unroll
                for (int nf = 0; nf < 8; nf++) {
                    const uint32_t* bhf = &bh_[nf >> 1][(nf & 1) * 2];
                    const uint32_t* blf = &bl_[nf >> 1][(nf & 1) * 2];
                    mma16816(oacc[mf][nf], ash[mf], bhf);
                    mma16816(oacc[mf][nf], asl[mf], bhf);
                    mma16816(oacc[mf][nf], ash[mf], blf);
                }
        }
    }

    // ---- cross-wlo reduction (scratch over Q area, stride 66) ----
    __syncthreads();
    if (wlo == 1) {
#pragma unroll
        for (int mf = 0; mf < 2; mf++)
#pragma unroll
            for (int nf = 0; nf < 8; nf++)
#pragma unroll
                for (int e = 0; e < 4; e++) {
                    int qloc = mf * 16 + g + 8 * (e >> 1);
                    int n = nf * 8 + 2 * t + (e & 1);
                    sw[wq * 2112 + qloc * 66 + n] = __float_as_uint(oacc[mf][nf][e]);
                }
    }
    __syncthreads();
    if (wlo == 0) {
#pragma unroll
        for (int mf = 0; mf < 2; mf++)
#pragma unroll
            for (int nf = 0; nf < 8; nf++)
#pragma unroll
                for (int half = 0; half < 2; half++) {
                    int qloc = mf * 16 + g + 8 * half;
                    int n = nf * 8 + 2 * t;
                    float sA = oacc[mf][nf][2 * half] +
                               __uint_as_float(sw[wq * 2112 + qloc * 66 + n]);
                    float sB = oacc[mf][nf][2 * half + 1] +
                               __uint_as_float(sw[wq * 2112 + qloc * 66 + n + 1]);
                    int row = q0 + wq * 32 + qloc;
                    int cc = h * 64 + n;
                    uint32_t hi, lo;
                    split_pair(sA, sB, hi, lo);
                    uint32_t* rowp = na + (size_t)(b * 2048 + row) * KWP;
                    rowp[(cc >> 1)] = hi;
                    rowp[512 + (cc >> 1)] = lo;
                }
    }
#undef KVISSUE
}

// ---------------- kernel_launch ----------------
extern "C" void kernel_launch(void* const* d_in, const int* in_sizes, int n_in,
                              void* d_out, int out_size)
{
    const float* x  = (const float*)d_in[0];
    const float* Wp = (const float*)d_in[1];
    const float* Wo = (const float*)d_in[2];
    float* out = (float*)d_out;

    float* vf;
    uint32_t *xa, *wpb, *wob, *na, *qk, *vth, *vtl;
    cudaGetSymbolAddress((void**)&vf,  g_v);
    cudaGetSymbolAddress((void**)&xa,  g_xa);
    cudaGetSymbolAddress((void**)&wpb, g_wpb);
    cudaGetSymbolAddress((void**)&wob, g_wob);
    cudaGetSymbolAddress((void**)&na,  g_na);
    cudaGetSymbolAddress((void**)&qk,  g_qk);
    cudaGetSymbolAddress((void**)&vth, g_vth);
    cudaGetSymbolAddress((void**)&vtl, g_vtl);

    cudaFuncSetAttribute(gemm_pl, cudaFuncAttributeMaxDynamicSharedMemorySize, GSMEMB);
    cudaFuncSetAttribute(attn_pl, cudaFuncAttributeMaxDynamicSharedMemorySize, ASMEMB);

    {
        int total = NTASK_X + NTASK_WP + NTASK_WO;
        pack_all<<<(total + 255) / 256, 256>>>(x, Wp, Wo, xa, wpb, wob);
    }

    // 1) proj GEMM; epilogue emits unified Q/K planes + V fp32 staging
    gemm_pl<<<dim3(2048 / 128, MROWS / 128), 256, GSMEMB>>>(
        xa, wpb, nullptr, 2048, 1, qk, vf);

    // V transpose -> hi/lo bf16 planes
    vt_pack<<<dim3(WTOT / 128, 32), 256>>>(vf, vth, vtl);

    // 2) fused causal attention; epilogue emits nudged planes
    attn_pl<<<dim3(32, 32), 128, ASMEMB>>>(qk, vth, vtl, na);

    // 3) output GEMM -> fp32 out
    gemm_pl<<<dim3(1024 / 128, MROWS / 128), 256, GSMEMB>>>(
        na, wob, out, 1024, 0, nullptr, nullptr);
}